// round 1
// baseline (speedup 1.0000x reference)
#include <cuda_runtime.h>
#include <math.h>

#define N 4096
#define D 1024
#define OUTD 1000
#define KSEL 819
#define BN_EPS 1e-5f

// ---------------- scratch (device globals; no allocations allowed) ----------
__device__ float g_sq[N];
__device__ float g_Ae[(size_t)N * N];      // 64 MiB gaussian affinity
__device__ float g_thr[N];                 // per-row K-th largest Ae value
__device__ float g_invd[N];                // 1/sqrt(2 + rowsum)
__device__ int   g_nnz[N];
__device__ int   g_cols[(size_t)N * N];    // sparse An off-diagonal (capacity N/row)
__device__ float g_vals[(size_t)N * N];
__device__ float g_S[(size_t)N * OUTD];    // support = F @ W
__device__ float g_t1[(size_t)N * OUTD];   // An @ S
__device__ float g_coef[3];                // softmax(aifa)

// ---------------- tiny kernels ----------------------------------------------
__global__ void aifa_kernel(const float* a1, const float* a2, const float* a3) {
    float x0 = a1[0], x1 = a2[0], x2 = a3[0];
    float m = fmaxf(x0, fmaxf(x1, x2));
    float e0 = expf(x0 - m), e1 = expf(x1 - m), e2 = expf(x2 - m);
    float s = e0 + e1 + e2;
    g_coef[0] = e0 / s; g_coef[1] = e1 / s; g_coef[2] = e2 / s;
}

__global__ void sq_kernel(const float* __restrict__ F) {
    int row = blockIdx.x, tid = threadIdx.x;
    float4 v = *(const float4*)(F + (size_t)row * D + tid * 4);
    float s = v.x * v.x + v.y * v.y + v.z * v.z + v.w * v.w;
    __shared__ float red[256];
    red[tid] = s; __syncthreads();
    for (int o = 128; o > 0; o >>= 1) {
        if (tid < o) red[tid] += red[tid + o];
        __syncthreads();
    }
    if (tid == 0) g_sq[row] = red[0];
}

// ---------------- Gram GEMM: Ae = exp(-max(sq_i+sq_j-2*F F^T, 0)/9) ---------
__global__ void __launch_bounds__(256) gram_kernel(const float* __restrict__ F) {
    __shared__ float As[8][132];
    __shared__ float Bs[8][132];
    int row0 = blockIdx.y * 128, col0 = blockIdx.x * 128;
    int tid = threadIdx.x;
    int lr = tid >> 1, lc = (tid & 1) * 4;
    int tx = tid & 15, ty = tid >> 4;
    float acc[8][8];
#pragma unroll
    for (int i = 0; i < 8; i++)
#pragma unroll
        for (int j = 0; j < 8; j++) acc[i][j] = 0.0f;

    const float* Aptr = F + (size_t)(row0 + lr) * D + lc;
    const float* Bptr = F + (size_t)(col0 + lr) * D + lc;

    for (int k0 = 0; k0 < D; k0 += 8) {
        float4 av = *(const float4*)(Aptr + k0);
        float4 bv = *(const float4*)(Bptr + k0);
        As[lc + 0][lr] = av.x; As[lc + 1][lr] = av.y;
        As[lc + 2][lr] = av.z; As[lc + 3][lr] = av.w;
        Bs[lc + 0][lr] = bv.x; Bs[lc + 1][lr] = bv.y;
        Bs[lc + 2][lr] = bv.z; Bs[lc + 3][lr] = bv.w;
        __syncthreads();
#pragma unroll
        for (int kk = 0; kk < 8; kk++) {
            float a[8], b[8];
            *(float4*)&a[0] = *(const float4*)&As[kk][ty * 8];
            *(float4*)&a[4] = *(const float4*)&As[kk][ty * 8 + 4];
            *(float4*)&b[0] = *(const float4*)&Bs[kk][tx * 8];
            *(float4*)&b[4] = *(const float4*)&Bs[kk][tx * 8 + 4];
#pragma unroll
            for (int i = 0; i < 8; i++)
#pragma unroll
                for (int j = 0; j < 8; j++) acc[i][j] += a[i] * b[j];
        }
        __syncthreads();
    }

#pragma unroll
    for (int i = 0; i < 8; i++) {
        int r = row0 + ty * 8 + i;
        float sr = g_sq[r];
#pragma unroll
        for (int j = 0; j < 8; j++) {
            int c = col0 + tx * 8 + j;
            float d2 = fmaxf(sr + g_sq[c] - 2.0f * acc[i][j], 0.0f);
            g_Ae[(size_t)r * N + c] = expf(-d2 / 9.0f);
        }
    }
}

// ---------------- per-row K-th largest (radix select on positive floats) ----
__global__ void select_kernel() {
    __shared__ unsigned v[N];      // 16 KB
    __shared__ int hist[256];
    __shared__ int s_bin, s_rem;
    int row = blockIdx.x, tid = threadIdx.x;
    for (int i = tid; i < N; i += 256)
        v[i] = __float_as_uint(g_Ae[(size_t)row * N + i]);
    __syncthreads();

    unsigned prefix = 0;
    int remaining = KSEL;
    for (int shift = 24; shift >= 0; shift -= 8) {
        hist[tid] = 0;
        __syncthreads();
        unsigned hm = (shift == 24) ? 0u : (0xFFFFFFFFu << (shift + 8));
        unsigned ph = prefix & hm;
        for (int i = tid; i < N; i += 256) {
            unsigned x = v[i];
            if ((x & hm) == ph) atomicAdd(&hist[(x >> shift) & 255], 1);
        }
        __syncthreads();
        if (tid == 0) {
            int rem = remaining;
            int b = 255;
            for (; b > 0; b--) {
                if (rem <= hist[b]) break;
                rem -= hist[b];
            }
            s_bin = b; s_rem = rem;
        }
        __syncthreads();
        prefix |= ((unsigned)s_bin) << shift;
        remaining = s_rem;
        __syncthreads();
    }
    if (tid == 0) g_thr[row] = __uint_as_float(prefix);
}

// ---------------- build sparse A (raw Ae vals), degrees ---------------------
// keep (i,j), i!=j, if Ae[i,j] >= thr_i && Ae[i,j] >= thr_j (Ae is bit-exact
// symmetric by construction) and Ae[i,j] > 0 (zero entries contribute nothing
// to A or to the degree sums, so dropping them is exact).
__global__ void build_kernel() {
    int row = blockIdx.x, tid = threadIdx.x;
    float ti = g_thr[row];
    __shared__ int   cnt[256];
    __shared__ float ssum[256];
    __shared__ int   excl[257];
    int base = tid * 16;
    int lc = 0; float ls = 0.0f;
    for (int jj = 0; jj < 16; jj++) {
        int j = base + jj;
        float w = g_Ae[(size_t)row * N + j];
        if (j != row && w > 0.0f && w >= ti && w >= g_thr[j]) { lc++; ls += w; }
    }
    cnt[tid] = lc; ssum[tid] = ls;
    __syncthreads();
    if (tid == 0) {
        int run = 0; float tot = 0.0f;
        for (int t = 0; t < 256; t++) { excl[t] = run; run += cnt[t]; tot += ssum[t]; }
        excl[256] = run;
        g_nnz[row]  = run;
        g_invd[row] = rsqrtf(2.0f + tot);   // d = sqrt(1 (diag) + rowsum + 1)
    }
    __syncthreads();
    int off = excl[tid];
    for (int jj = 0; jj < 16; jj++) {
        int j = base + jj;
        float w = g_Ae[(size_t)row * N + j];
        if (j != row && w > 0.0f && w >= ti && w >= g_thr[j]) {
            g_cols[(size_t)row * N + off] = j;
            g_vals[(size_t)row * N + off] = w;
            off++;
        }
    }
}

__global__ void scale_kernel() {   // An off-diag: val /= d_i * d_j
    int row = blockIdx.x;
    int nn = g_nnz[row];
    float di = g_invd[row];
    for (int e = threadIdx.x; e < nn; e += 256) {
        size_t idx = (size_t)row * N + e;
        g_vals[idx] *= di * g_invd[g_cols[idx]];
    }
}

// ---------------- support GEMM: S = F(4096x1024) @ W(1024x1000) -------------
__global__ void __launch_bounds__(256) gemm_support(const float* __restrict__ A,
                                                    const float* __restrict__ B) {
    __shared__ float As[8][132];
    __shared__ float Bs[8][132];
    int row0 = blockIdx.y * 128, col0 = blockIdx.x * 128;
    int tid = threadIdx.x;
    int lrA = tid >> 1, lcA = (tid & 1) * 4;
    int lrB = tid >> 5, lcB = (tid & 31) * 4;
    int tx = tid & 15, ty = tid >> 4;
    float acc[8][8];
#pragma unroll
    for (int i = 0; i < 8; i++)
#pragma unroll
        for (int j = 0; j < 8; j++) acc[i][j] = 0.0f;

    const float* Aptr = A + (size_t)(row0 + lrA) * D + lcA;
    int bc = col0 + lcB;

    for (int k0 = 0; k0 < D; k0 += 8) {
        float4 av = *(const float4*)(Aptr + k0);
        As[lcA + 0][lrA] = av.x; As[lcA + 1][lrA] = av.y;
        As[lcA + 2][lrA] = av.z; As[lcA + 3][lrA] = av.w;
        float4 bv = make_float4(0.f, 0.f, 0.f, 0.f);
        if (bc < OUTD)  // OUTD % 4 == 0, bc % 4 == 0 -> full float4 in-bounds
            bv = *(const float4*)(B + (size_t)(k0 + lrB) * OUTD + bc);
        *(float4*)&Bs[lrB][lcB] = bv;
        __syncthreads();
#pragma unroll
        for (int kk = 0; kk < 8; kk++) {
            float a[8], b[8];
            *(float4*)&a[0] = *(const float4*)&As[kk][ty * 8];
            *(float4*)&a[4] = *(const float4*)&As[kk][ty * 8 + 4];
            *(float4*)&b[0] = *(const float4*)&Bs[kk][tx * 8];
            *(float4*)&b[4] = *(const float4*)&Bs[kk][tx * 8 + 4];
#pragma unroll
            for (int i = 0; i < 8; i++)
#pragma unroll
                for (int j = 0; j < 8; j++) acc[i][j] += a[i] * b[j];
        }
        __syncthreads();
    }

#pragma unroll
    for (int i = 0; i < 8; i++) {
        int r = row0 + ty * 8 + i;
#pragma unroll
        for (int j = 0; j < 8; j++) {
            int c = col0 + tx * 8 + j;
            if (c < OUTD) g_S[(size_t)r * OUTD + c] = acc[i][j];
        }
    }
}

// ---------------- sparse propagation: An @ X ---------------------------------
// MODE 0: t1 = An @ S
// MODE 1: out = relu(BN(c0*S + c1*t1 + c2*(An @ t1) + bias))
template <int MODE>
__global__ void spmm_kernel(const float* __restrict__ bias,
                            const float* __restrict__ gamma,
                            const float* __restrict__ beta,
                            const float* __restrict__ mean,
                            const float* __restrict__ var,
                            float* __restrict__ out) {
    int row = blockIdx.x, tid = threadIdx.x;
    float di = g_invd[row];
    float diag = di * di;                     // An[i,i] = 1/d_i^2
    const float* X = (MODE == 0) ? g_S : g_t1;
    const float* Xrow = X + (size_t)row * OUTD;
    int n0 = tid, n1 = tid + 256, n2 = tid + 512, n3 = tid + 768;
    float a0 = diag * Xrow[n0];
    float a1 = diag * Xrow[n1];
    float a2 = diag * Xrow[n2];
    float a3 = (n3 < OUTD) ? diag * Xrow[n3] : 0.0f;

    int nn = g_nnz[row];
    for (int e = 0; e < nn; e++) {
        float v = g_vals[(size_t)row * N + e];
        const float* Xc = X + (size_t)g_cols[(size_t)row * N + e] * OUTD;
        a0 += v * Xc[n0];
        a1 += v * Xc[n1];
        a2 += v * Xc[n2];
        if (n3 < OUTD) a3 += v * Xc[n3];
    }

    if (MODE == 0) {
        float* T = g_t1 + (size_t)row * OUTD;
        T[n0] = a0; T[n1] = a1; T[n2] = a2;
        if (n3 < OUTD) T[n3] = a3;
    } else {
        float c0 = g_coef[0], c1 = g_coef[1], c2 = g_coef[2];
        const float* Srow = g_S + (size_t)row * OUTD;
        const float* Trow = g_t1 + (size_t)row * OUTD;
        float* Orow = out + (size_t)row * OUTD;
        int ns[4] = {n0, n1, n2, n3};
        float as[4] = {a0, a1, a2, a3};
#pragma unroll
        for (int r = 0; r < 4; r++) {
            int n = ns[r];
            if (n < OUTD) {
                float x = c0 * Srow[n] + c1 * Trow[n] + c2 * as[r] + bias[n];
                float y = (x - mean[n]) * rsqrtf(var[n] + BN_EPS) * gamma[n] + beta[n];
                Orow[n] = fmaxf(y, 0.0f);
            }
        }
    }
}

// ---------------- launch -----------------------------------------------------
extern "C" void kernel_launch(void* const* d_in, const int* in_sizes, int n_in,
                              void* d_out, int out_size) {
    const float* F     = (const float*)d_in[0];
    const float* W     = (const float*)d_in[1];
    const float* bias  = (const float*)d_in[2];
    const float* a1    = (const float*)d_in[3];
    const float* a2    = (const float*)d_in[4];
    const float* a3    = (const float*)d_in[5];
    const float* gamma = (const float*)d_in[6];
    const float* beta  = (const float*)d_in[7];
    const float* mean  = (const float*)d_in[8];
    const float* var   = (const float*)d_in[9];
    float* out = (float*)d_out;

    aifa_kernel<<<1, 1>>>(a1, a2, a3);
    sq_kernel<<<N, 256>>>(F);
    gram_kernel<<<dim3(32, 32), 256>>>(F);
    select_kernel<<<N, 256>>>();
    build_kernel<<<N, 256>>>();
    scale_kernel<<<N, 256>>>();
    gemm_support<<<dim3(8, 32), 256>>>(F, W);
    spmm_kernel<0><<<N, 256>>>(bias, gamma, beta, mean, var, out);
    spmm_kernel<1><<<N, 256>>>(bias, gamma, beta, mean, var, out);
}

// round 2
// speedup vs baseline: 1.3363x; 1.3363x over previous
#include <cuda_runtime.h>
#include <math.h>

#define N 4096
#define D 1024
#define OUTD 1000
#define KSEL 819
#define BN_EPS 1e-5f

// ---------------- scratch (device globals; no allocations allowed) ----------
__device__ float g_sq[N];
__device__ float g_Ae[(size_t)N * N];      // 64 MiB gaussian affinity
__device__ float g_thr[N];                 // per-row K-th largest Ae value
__device__ float g_invd[N];                // 1/sqrt(2 + rowsum)
__device__ int   g_nnz[N];
__device__ int   g_cols[(size_t)N * N];    // sparse An off-diagonal (capacity N/row)
__device__ float g_vals[(size_t)N * N];
__device__ float g_S[(size_t)N * OUTD];    // support = F @ W
__device__ float g_t1[(size_t)N * OUTD];   // An @ S
__device__ float g_coef[3];                // softmax(aifa)

// ---------------- tiny kernels ----------------------------------------------
__global__ void aifa_kernel(const float* a1, const float* a2, const float* a3) {
    float x0 = a1[0], x1 = a2[0], x2 = a3[0];
    float m = fmaxf(x0, fmaxf(x1, x2));
    float e0 = expf(x0 - m), e1 = expf(x1 - m), e2 = expf(x2 - m);
    float s = e0 + e1 + e2;
    g_coef[0] = e0 / s; g_coef[1] = e1 / s; g_coef[2] = e2 / s;
}

__global__ void sq_kernel(const float* __restrict__ F) {
    int row = blockIdx.x, tid = threadIdx.x;
    float4 v = *(const float4*)(F + (size_t)row * D + tid * 4);
    float s = v.x * v.x + v.y * v.y + v.z * v.z + v.w * v.w;
    __shared__ float red[256];
    red[tid] = s; __syncthreads();
    for (int o = 128; o > 0; o >>= 1) {
        if (tid < o) red[tid] += red[tid + o];
        __syncthreads();
    }
    if (tid == 0) g_sq[row] = red[0];
}

// ---------------- Gram GEMM (lower-triangular tiles + mirrored stores) ------
// Ae = exp(-max(sq_i + sq_j - 2*F F^T, 0)/9); Ae is bit-exactly symmetric
// (identical product sequence in identical k-order for (i,j) and (j,i)), so we
// compute only tile pairs (tr >= tc) and store both halves.
__global__ void __launch_bounds__(256) gram_kernel(const float* __restrict__ F) {
    __shared__ float As[8][132];
    __shared__ float Bs[8][132];

    // map linear block id -> lower-triangular tile (tr, tc), tr >= tc
    int bid = blockIdx.x;
    int tr = (int)((sqrtf(8.0f * (float)bid + 1.0f) - 1.0f) * 0.5f);
    while ((tr + 1) * (tr + 2) / 2 <= bid) tr++;
    while (tr * (tr + 1) / 2 > bid) tr--;
    int tc = bid - tr * (tr + 1) / 2;

    int row0 = tr * 128, col0 = tc * 128;
    int tid = threadIdx.x;
    int lr = tid >> 1, lc = (tid & 1) * 4;
    int tx = tid & 15, ty = tid >> 4;
    float acc[8][8];
#pragma unroll
    for (int i = 0; i < 8; i++)
#pragma unroll
        for (int j = 0; j < 8; j++) acc[i][j] = 0.0f;

    const float* Aptr = F + (size_t)(row0 + lr) * D + lc;
    const float* Bptr = F + (size_t)(col0 + lr) * D + lc;

    for (int k0 = 0; k0 < D; k0 += 8) {
        float4 av = *(const float4*)(Aptr + k0);
        float4 bv = *(const float4*)(Bptr + k0);
        As[lc + 0][lr] = av.x; As[lc + 1][lr] = av.y;
        As[lc + 2][lr] = av.z; As[lc + 3][lr] = av.w;
        Bs[lc + 0][lr] = bv.x; Bs[lc + 1][lr] = bv.y;
        Bs[lc + 2][lr] = bv.z; Bs[lc + 3][lr] = bv.w;
        __syncthreads();
#pragma unroll
        for (int kk = 0; kk < 8; kk++) {
            float a[8], b[8];
            *(float4*)&a[0] = *(const float4*)&As[kk][ty * 8];
            *(float4*)&a[4] = *(const float4*)&As[kk][ty * 8 + 4];
            *(float4*)&b[0] = *(const float4*)&Bs[kk][tx * 8];
            *(float4*)&b[4] = *(const float4*)&Bs[kk][tx * 8 + 4];
#pragma unroll
            for (int i = 0; i < 8; i++)
#pragma unroll
                for (int j = 0; j < 8; j++) acc[i][j] += a[i] * b[j];
        }
        __syncthreads();
    }

#pragma unroll
    for (int i = 0; i < 8; i++) {
        int r = row0 + ty * 8 + i;
        float sr = g_sq[r];
#pragma unroll
        for (int j = 0; j < 8; j++) {
            int c = col0 + tx * 8 + j;
            float d2 = fmaxf(sr + g_sq[c] - 2.0f * acc[i][j], 0.0f);
            float e = expf(-d2 / 9.0f);
            g_Ae[(size_t)r * N + c] = e;
            g_Ae[(size_t)c * N + r] = e;   // mirror (diag tiles: same-value dup)
        }
    }
}

// ---------------- per-row K-th largest (radix select on positive floats) ----
// warp-aggregated histogram (match_any) + parallel suffix-sum bin search.
__global__ void select_kernel() {
    __shared__ unsigned v[N];      // 16 KB
    __shared__ int hist[256];
    __shared__ int sfx[256];
    __shared__ int s_bin, s_rem;
    int row = blockIdx.x, tid = threadIdx.x;
    int lane = tid & 31;
    for (int i = tid; i < N; i += 256)
        v[i] = __float_as_uint(g_Ae[(size_t)row * N + i]);
    __syncthreads();

    unsigned prefix = 0;
    int remaining = KSEL;
    for (int shift = 24; shift >= 0; shift -= 8) {
        hist[tid] = 0;
        __syncthreads();
        unsigned hm = (shift == 24) ? 0u : (0xFFFFFFFFu << (shift + 8));
        unsigned ph = prefix & hm;
#pragma unroll
        for (int i = tid; i < N; i += 256) {
            unsigned x = v[i];
            bool act = ((x & hm) == ph);
            int bin = (x >> shift) & 255;
            unsigned key = act ? (unsigned)bin : 0xFFFFFFFFu;
            unsigned mask = __match_any_sync(0xFFFFFFFFu, key);
            if (act && ((__ffs(mask) - 1) == lane))
                atomicAdd(&hist[bin], __popc(mask));
        }
        __syncthreads();
        // suffix sums: sfx[t] = sum(hist[t..255])
        sfx[tid] = hist[tid];
        __syncthreads();
        for (int off = 1; off < 256; off <<= 1) {
            int val = (tid + off < 256) ? sfx[tid + off] : 0;
            __syncthreads();
            sfx[tid] += val;
            __syncthreads();
        }
        // unique b: sfx[b] >= remaining > sfx[b+1]
        int nb = (tid < 255) ? sfx[tid + 1] : 0;
        if (sfx[tid] >= remaining && nb < remaining) {
            s_bin = tid;
            s_rem = remaining - nb;
        }
        __syncthreads();
        prefix |= ((unsigned)s_bin) << shift;
        remaining = s_rem;
        __syncthreads();
    }
    if (tid == 0) g_thr[row] = __uint_as_float(prefix);
}

// ---------------- build sparse A (raw Ae vals), degrees ---------------------
__global__ void build_kernel() {
    int row = blockIdx.x, tid = threadIdx.x;
    float ti = g_thr[row];
    __shared__ int   cnt[256];
    __shared__ float ssum[256];
    __shared__ int   excl[257];
    int base = tid * 16;
    int lc = 0; float ls = 0.0f;
    for (int jj = 0; jj < 16; jj++) {
        int j = base + jj;
        float w = g_Ae[(size_t)row * N + j];
        if (j != row && w > 0.0f && w >= ti && w >= g_thr[j]) { lc++; ls += w; }
    }
    cnt[tid] = lc; ssum[tid] = ls;
    __syncthreads();
    if (tid == 0) {
        int run = 0; float tot = 0.0f;
        for (int t = 0; t < 256; t++) { excl[t] = run; run += cnt[t]; tot += ssum[t]; }
        excl[256] = run;
        g_nnz[row]  = run;
        g_invd[row] = rsqrtf(2.0f + tot);   // d = sqrt(1 (diag) + rowsum + 1)
    }
    __syncthreads();
    int off = excl[tid];
    for (int jj = 0; jj < 16; jj++) {
        int j = base + jj;
        float w = g_Ae[(size_t)row * N + j];
        if (j != row && w > 0.0f && w >= ti && w >= g_thr[j]) {
            g_cols[(size_t)row * N + off] = j;
            g_vals[(size_t)row * N + off] = w;
            off++;
        }
    }
}

__global__ void scale_kernel() {   // An off-diag: val /= d_i * d_j
    int row = blockIdx.x;
    int nn = g_nnz[row];
    float di = g_invd[row];
    for (int e = threadIdx.x; e < nn; e += 256) {
        size_t idx = (size_t)row * N + e;
        g_vals[idx] *= di * g_invd[g_cols[idx]];
    }
}

// ---------------- support GEMM: S = F(4096x1024) @ W(1024x1000) -------------
__global__ void __launch_bounds__(256) gemm_support(const float* __restrict__ A,
                                                    const float* __restrict__ B) {
    __shared__ float As[8][132];
    __shared__ float Bs[8][132];
    int row0 = blockIdx.y * 128, col0 = blockIdx.x * 128;
    int tid = threadIdx.x;
    int lrA = tid >> 1, lcA = (tid & 1) * 4;
    int lrB = tid >> 5, lcB = (tid & 31) * 4;
    int tx = tid & 15, ty = tid >> 4;
    float acc[8][8];
#pragma unroll
    for (int i = 0; i < 8; i++)
#pragma unroll
        for (int j = 0; j < 8; j++) acc[i][j] = 0.0f;

    const float* Aptr = A + (size_t)(row0 + lrA) * D + lcA;
    int bc = col0 + lcB;

    for (int k0 = 0; k0 < D; k0 += 8) {
        float4 av = *(const float4*)(Aptr + k0);
        As[lcA + 0][lrA] = av.x; As[lcA + 1][lrA] = av.y;
        As[lcA + 2][lrA] = av.z; As[lcA + 3][lrA] = av.w;
        float4 bv = make_float4(0.f, 0.f, 0.f, 0.f);
        if (bc < OUTD)
            bv = *(const float4*)(B + (size_t)(k0 + lrB) * OUTD + bc);
        *(float4*)&Bs[lrB][lcB] = bv;
        __syncthreads();
#pragma unroll
        for (int kk = 0; kk < 8; kk++) {
            float a[8], b[8];
            *(float4*)&a[0] = *(const float4*)&As[kk][ty * 8];
            *(float4*)&a[4] = *(const float4*)&As[kk][ty * 8 + 4];
            *(float4*)&b[0] = *(const float4*)&Bs[kk][tx * 8];
            *(float4*)&b[4] = *(const float4*)&Bs[kk][tx * 8 + 4];
#pragma unroll
            for (int i = 0; i < 8; i++)
#pragma unroll
                for (int j = 0; j < 8; j++) acc[i][j] += a[i] * b[j];
        }
        __syncthreads();
    }

#pragma unroll
    for (int i = 0; i < 8; i++) {
        int r = row0 + ty * 8 + i;
#pragma unroll
        for (int j = 0; j < 8; j++) {
            int c = col0 + tx * 8 + j;
            if (c < OUTD) g_S[(size_t)r * OUTD + c] = acc[i][j];
        }
    }
}

// ---------------- sparse propagation: An @ X ---------------------------------
template <int MODE>
__global__ void spmm_kernel(const float* __restrict__ bias,
                            const float* __restrict__ gamma,
                            const float* __restrict__ beta,
                            const float* __restrict__ mean,
                            const float* __restrict__ var,
                            float* __restrict__ out) {
    int row = blockIdx.x, tid = threadIdx.x;
    float di = g_invd[row];
    float diag = di * di;                     // An[i,i] = 1/d_i^2
    const float* X = (MODE == 0) ? g_S : g_t1;
    const float* Xrow = X + (size_t)row * OUTD;
    int n0 = tid, n1 = tid + 256, n2 = tid + 512, n3 = tid + 768;
    float a0 = diag * Xrow[n0];
    float a1 = diag * Xrow[n1];
    float a2 = diag * Xrow[n2];
    float a3 = (n3 < OUTD) ? diag * Xrow[n3] : 0.0f;

    int nn = g_nnz[row];
    for (int e = 0; e < nn; e++) {
        float v = g_vals[(size_t)row * N + e];
        const float* Xc = X + (size_t)g_cols[(size_t)row * N + e] * OUTD;
        a0 += v * Xc[n0];
        a1 += v * Xc[n1];
        a2 += v * Xc[n2];
        if (n3 < OUTD) a3 += v * Xc[n3];
    }

    if (MODE == 0) {
        float* T = g_t1 + (size_t)row * OUTD;
        T[n0] = a0; T[n1] = a1; T[n2] = a2;
        if (n3 < OUTD) T[n3] = a3;
    } else {
        float c0 = g_coef[0], c1 = g_coef[1], c2 = g_coef[2];
        const float* Srow = g_S + (size_t)row * OUTD;
        const float* Trow = g_t1 + (size_t)row * OUTD;
        float* Orow = out + (size_t)row * OUTD;
        int ns[4] = {n0, n1, n2, n3};
        float as[4] = {a0, a1, a2, a3};
#pragma unroll
        for (int r = 0; r < 4; r++) {
            int n = ns[r];
            if (n < OUTD) {
                float x = c0 * Srow[n] + c1 * Trow[n] + c2 * as[r] + bias[n];
                float y = (x - mean[n]) * rsqrtf(var[n] + BN_EPS) * gamma[n] + beta[n];
                Orow[n] = fmaxf(y, 0.0f);
            }
        }
    }
}

// ---------------- launch -----------------------------------------------------
extern "C" void kernel_launch(void* const* d_in, const int* in_sizes, int n_in,
                              void* d_out, int out_size) {
    const float* F     = (const float*)d_in[0];
    const float* W     = (const float*)d_in[1];
    const float* bias  = (const float*)d_in[2];
    const float* a1    = (const float*)d_in[3];
    const float* a2    = (const float*)d_in[4];
    const float* a3    = (const float*)d_in[5];
    const float* gamma = (const float*)d_in[6];
    const float* beta  = (const float*)d_in[7];
    const float* mean  = (const float*)d_in[8];
    const float* var   = (const float*)d_in[9];
    float* out = (float*)d_out;

    aifa_kernel<<<1, 1>>>(a1, a2, a3);
    sq_kernel<<<N, 256>>>(F);
    gram_kernel<<<528, 256>>>(F);              // lower-triangular tiles only
    select_kernel<<<N, 256>>>();
    build_kernel<<<N, 256>>>();
    scale_kernel<<<N, 256>>>();
    gemm_support<<<dim3(8, 32), 256>>>(F, W);
    spmm_kernel<0><<<N, 256>>>(bias, gamma, beta, mean, var, out);
    spmm_kernel<1><<<N, 256>>>(bias, gamma, beta, mean, var, out);
}

// round 4
// speedup vs baseline: 2.8687x; 2.1467x over previous
#include <cuda_runtime.h>
#include <cuda_bf16.h>
#include <math.h>
#include <stdint.h>

#define N 4096
#define D 1024
#define OUTD 1000
#define KSEL 819
#define BN_EPS 1e-5f

// ---------------- scratch (device globals; no allocations allowed) ----------
__device__ float g_sq[N];
__device__ __nv_bfloat16 g_Fbf[(size_t)N * D];  // bf16 copy of features (8 MB)
__device__ float g_Ae[(size_t)N * N];      // 64 MiB gaussian affinity
__device__ float g_thr[N];                 // per-row K-th largest Ae value
__device__ float g_invd[N];                // 1/sqrt(2 + rowsum)
__device__ int   g_nnz[N];
__device__ int   g_cols[(size_t)N * N];
__device__ float g_vals[(size_t)N * N];
__device__ float g_S[(size_t)N * OUTD];    // support = F @ W
__device__ float g_t1[(size_t)N * OUTD];   // An @ S
__device__ float g_coef[3];                // softmax(aifa)
__device__ int   g_sel_cnt;                // rows needing full radix select
__device__ int   g_sel_rows[N];

// ---------------- baseline-PTX tensor-core helpers (no sm_103a features) ----
__device__ __forceinline__ uint32_t smem_u32(const void* p) {
    uint32_t a;
    asm("{ .reg .u64 t; cvta.to.shared.u64 t, %1; cvt.u32.u64 %0, t; }"
        : "=r"(a) : "l"(p));
    return a;
}
#define CP_ASYNC16(dst, src) \
    asm volatile("cp.async.cg.shared.global [%0], [%1], 16;" :: "r"(dst), "l"(src) : "memory")
#define CP_COMMIT() asm volatile("cp.async.commit_group;" ::: "memory")
#define CP_WAIT(n)  asm volatile("cp.async.wait_group %0;" :: "n"(n) : "memory")
#define LDMX4(r0, r1, r2, r3, addr) \
    asm volatile("ldmatrix.sync.aligned.m8n8.x4.shared.b16 {%0,%1,%2,%3}, [%4];" \
                 : "=r"(r0), "=r"(r1), "=r"(r2), "=r"(r3) : "r"(addr))
#define MMA16816(d, a, b0v, b1v) \
    asm volatile("mma.sync.aligned.m16n8k16.row.col.f32.bf16.bf16.f32 " \
                 "{%0,%1,%2,%3}, {%4,%5,%6,%7}, {%8,%9}, {%0,%1,%2,%3};" \
                 : "+f"((d)[0]), "+f"((d)[1]), "+f"((d)[2]), "+f"((d)[3]) \
                 : "r"((a)[0]), "r"((a)[1]), "r"((a)[2]), "r"((a)[3]), \
                   "r"(b0v), "r"(b1v))

// ---------------- tiny kernels ----------------------------------------------
__global__ void aifa_kernel(const float* a1, const float* a2, const float* a3) {
    float x0 = a1[0], x1 = a2[0], x2 = a3[0];
    float m = fmaxf(x0, fmaxf(x1, x2));
    float e0 = expf(x0 - m), e1 = expf(x1 - m), e2 = expf(x2 - m);
    float s = e0 + e1 + e2;
    g_coef[0] = e0 / s; g_coef[1] = e1 / s; g_coef[2] = e2 / s;
    g_sel_cnt = 0;
}

__global__ void sq_kernel(const float* __restrict__ F) {
    int row = blockIdx.x, tid = threadIdx.x;
    float4 v = *(const float4*)(F + (size_t)row * D + tid * 4);
    float s = v.x * v.x + v.y * v.y + v.z * v.z + v.w * v.w;
    __shared__ float red[256];
    red[tid] = s; __syncthreads();
    for (int o = 128; o > 0; o >>= 1) {
        if (tid < o) red[tid] += red[tid + o];
        __syncthreads();
    }
    if (tid == 0) g_sq[row] = red[0];
}

__global__ void tobf16_kernel(const float* __restrict__ F) {
    int i = blockIdx.x * 1024 + threadIdx.x * 4;
    float4 v = *(const float4*)(F + i);
    __nv_bfloat162 p0, p1;
    p0.x = __float2bfloat16(v.x); p0.y = __float2bfloat16(v.y);
    p1.x = __float2bfloat16(v.z); p1.y = __float2bfloat16(v.w);
    *(__nv_bfloat162*)(g_Fbf + i)     = p0;
    *(__nv_bfloat162*)(g_Fbf + i + 2) = p1;
}

// ---------------- mma.sync Gram: lower-tri 128x128 bf16 tiles ---------------
// gram = Fb[rows] @ Fb[cols]^T (fp32 accum); epilogue exp(-max(...,0)/9),
// stores tile + mirror. CTA 128x128, 8 warps of 32x64, KC=32 double-buffered
// cp.async pipeline. Smem bf16 stride 40 (80 B) -> conflict-free ldmatrix.
#define KC 32
#define NC (D / KC)
#define SAB 40
#define TILE_B (128 * SAB * 2)     // 10240 bytes per operand tile

__global__ void __launch_bounds__(256) gram_mma_kernel() {
    extern __shared__ char smem[];
    uint32_t sb = smem_u32(smem);
    int tid = threadIdx.x, wid = tid >> 5, lane = tid & 31;

    // triangular tile decode
    int bid = blockIdx.x;
    int tr = (int)((sqrtf(8.0f * (float)bid + 1.0f) - 1.0f) * 0.5f);
    while ((tr + 1) * (tr + 2) / 2 <= bid) tr++;
    while (tr * (tr + 1) / 2 > bid) tr--;
    int tc = bid - tr * (tr + 1) / 2;
    int row0 = tr * 128, col0 = tc * 128;

    const __nv_bfloat16* Ag = g_Fbf + (size_t)row0 * D;
    const __nv_bfloat16* Bg = g_Fbf + (size_t)col0 * D;

    float acc[2][8][4];
#pragma unroll
    for (int i = 0; i < 2; i++)
#pragma unroll
        for (int j = 0; j < 8; j++)
#pragma unroll
            for (int d = 0; d < 4; d++) acc[i][j][d] = 0.0f;

    int ldr = tid >> 2, lds = tid & 3;          // row, 16B-segment for cp.async

    auto issue = [&](int c) {
        int s = c & 1;
        uint32_t dstA = sb + s * (2 * TILE_B);
        uint32_t dstB = dstA + TILE_B;
        int k0 = c * KC;
#pragma unroll
        for (int h = 0; h < 2; h++) {
            int r = ldr + h * 64;
            uint32_t off = (uint32_t)r * (SAB * 2) + lds * 16;
            CP_ASYNC16(dstA + off, (const void*)(Ag + (size_t)r * D + k0 + lds * 8));
            CP_ASYNC16(dstB + off, (const void*)(Bg + (size_t)r * D + k0 + lds * 8));
        }
    };

    int wm = wid & 3, wn = wid >> 2;
    // ldmatrix lane address components
    int a_row = (lane & 7) + ((lane >> 3) & 1) * 8;
    int a_col = ((lane >> 4) & 1) * 8;
    int b_row = (lane & 7) + ((lane >> 4) & 1) * 8;
    int b_col = ((lane >> 3) & 1) * 8;

    issue(0); CP_COMMIT();
    for (int c = 0; c < NC; c++) {
        if (c + 1 < NC) { issue(c + 1); CP_COMMIT(); CP_WAIT(1); }
        else            { CP_WAIT(0); }
        __syncthreads();

        int s = c & 1;
        uint32_t Abase = sb + s * (2 * TILE_B) + (uint32_t)(wm * 32) * (SAB * 2);
        uint32_t Bbase = sb + s * (2 * TILE_B) + TILE_B + (uint32_t)(wn * 64) * (SAB * 2);

        uint32_t a[2][2][4];
#pragma unroll
        for (int i = 0; i < 2; i++)
#pragma unroll
            for (int st = 0; st < 2; st++) {
                uint32_t ad = Abase + (uint32_t)(i * 16 + a_row) * (SAB * 2)
                            + (uint32_t)(st * 16 + a_col) * 2;
                LDMX4(a[i][st][0], a[i][st][1], a[i][st][2], a[i][st][3], ad);
            }
        uint32_t b[4][2][4];
#pragma unroll
        for (int jp = 0; jp < 4; jp++)
#pragma unroll
            for (int st = 0; st < 2; st++) {
                uint32_t bd = Bbase + (uint32_t)(jp * 16 + b_row) * (SAB * 2)
                            + (uint32_t)(st * 16 + b_col) * 2;
                LDMX4(b[jp][st][0], b[jp][st][1], b[jp][st][2], b[jp][st][3], bd);
            }
#pragma unroll
        for (int i = 0; i < 2; i++)
#pragma unroll
            for (int j = 0; j < 8; j++) {
                int jp = j >> 1, hf = (j & 1) * 2;
#pragma unroll
                for (int st = 0; st < 2; st++)
                    MMA16816(acc[i][j], a[i][st], b[jp][st][hf], b[jp][st][hf + 1]);
            }
        __syncthreads();
    }

    // epilogue: exp into smem [128][133], then coalesced + mirrored stores
    float* epi = (float*)smem;
    int er = lane >> 2, ec = (lane & 3) * 2;
#pragma unroll
    for (int i = 0; i < 2; i++)
#pragma unroll
        for (int j = 0; j < 8; j++)
#pragma unroll
            for (int d = 0; d < 4; d++) {
                int r = wm * 32 + i * 16 + (d >> 1) * 8 + er;
                int cc = wn * 64 + j * 8 + ec + (d & 1);
                float d2 = fmaxf(g_sq[row0 + r] + g_sq[col0 + cc] - 2.0f * acc[i][j][d], 0.0f);
                epi[r * 133 + cc] = expf(-d2 / 9.0f);
            }
    __syncthreads();

    for (int rr = wid * 16; rr < wid * 16 + 16; rr++) {
        float4 v;
        v.x = epi[rr * 133 + lane * 4 + 0];
        v.y = epi[rr * 133 + lane * 4 + 1];
        v.z = epi[rr * 133 + lane * 4 + 2];
        v.w = epi[rr * 133 + lane * 4 + 3];
        *(float4*)(g_Ae + (size_t)(row0 + rr) * N + col0 + lane * 4) = v;
    }
    for (int cc = wid * 16; cc < wid * 16 + 16; cc++) {
        float4 v;
        v.x = epi[(lane * 4 + 0) * 133 + cc];
        v.y = epi[(lane * 4 + 1) * 133 + cc];
        v.z = epi[(lane * 4 + 2) * 133 + cc];
        v.w = epi[(lane * 4 + 3) * 133 + cc];
        *(float4*)(g_Ae + (size_t)(col0 + cc) * N + row0 + lane * 4) = v;
    }
}

// ---------------- select fast path: count positives per row -----------------
__global__ void count_kernel() {
    int row = blockIdx.x, tid = threadIdx.x;
    const float* R = g_Ae + (size_t)row * N;
    int c = 0;
#pragma unroll
    for (int i = 0; i < 4; i++) {
        float4 v = *(const float4*)(R + tid * 16 + i * 4);
        c += (v.x > 0.0f) + (v.y > 0.0f) + (v.z > 0.0f) + (v.w > 0.0f);
    }
    for (int o = 16; o > 0; o >>= 1) c += __shfl_xor_sync(0xFFFFFFFFu, c, o);
    __shared__ int ws[8];
    if ((tid & 31) == 0) ws[tid >> 5] = c;
    __syncthreads();
    if (tid == 0) {
        int t = 0;
        for (int i = 0; i < 8; i++) t += ws[i];
        if (t < KSEL) {
            g_thr[row] = 0.0f;     // K-th largest is one of the zeros
        } else {
            int idx = atomicAdd(&g_sel_cnt, 1);
            g_sel_rows[idx] = row;
        }
    }
}

// ---------------- full radix select (only rows with >= K positives) ---------
__global__ void select_kernel() {
    __shared__ unsigned v[N];
    __shared__ int hist[256];
    __shared__ int sfx[256];
    __shared__ int s_bin, s_rem;
    if (blockIdx.x >= g_sel_cnt) return;
    int row = g_sel_rows[blockIdx.x];
    int tid = threadIdx.x, lane = tid & 31;
    for (int i = tid; i < N; i += 256)
        v[i] = __float_as_uint(g_Ae[(size_t)row * N + i]);
    __syncthreads();

    unsigned prefix = 0;
    int remaining = KSEL;
    for (int shift = 24; shift >= 0; shift -= 8) {
        hist[tid] = 0;
        __syncthreads();
        unsigned hm = (shift == 24) ? 0u : (0xFFFFFFFFu << (shift + 8));
        unsigned ph = prefix & hm;
#pragma unroll
        for (int i = tid; i < N; i += 256) {
            unsigned x = v[i];
            bool act = ((x & hm) == ph);
            int bin = (x >> shift) & 255;
            unsigned key = act ? (unsigned)bin : 0xFFFFFFFFu;
            unsigned mask = __match_any_sync(0xFFFFFFFFu, key);
            if (act && ((__ffs(mask) - 1) == lane))
                atomicAdd(&hist[bin], __popc(mask));
        }
        __syncthreads();
        sfx[tid] = hist[tid];
        __syncthreads();
        for (int off = 1; off < 256; off <<= 1) {
            int val = (tid + off < 256) ? sfx[tid + off] : 0;
            __syncthreads();
            sfx[tid] += val;
            __syncthreads();
        }
        int nb = (tid < 255) ? sfx[tid + 1] : 0;
        if (sfx[tid] >= remaining && nb < remaining) {
            s_bin = tid;
            s_rem = remaining - nb;
        }
        __syncthreads();
        prefix |= ((unsigned)s_bin) << shift;
        remaining = s_rem;
        __syncthreads();
    }
    if (tid == 0) g_thr[row] = __uint_as_float(prefix);
}

// ---------------- build sparse A (raw Ae vals), degrees ---------------------
__global__ void build_kernel() {
    int row = blockIdx.x, tid = threadIdx.x;
    float ti = g_thr[row];
    __shared__ int   cnt[256];
    __shared__ float ssum[256];
    __shared__ int   excl[257];
    int base = tid * 16;
    int lc = 0; float ls = 0.0f;
    for (int jj = 0; jj < 16; jj++) {
        int j = base + jj;
        float w = g_Ae[(size_t)row * N + j];
        if (j != row && w > 0.0f && w >= ti && w >= g_thr[j]) { lc++; ls += w; }
    }
    cnt[tid] = lc; ssum[tid] = ls;
    __syncthreads();
    if (tid == 0) {
        int run = 0; float tot = 0.0f;
        for (int t = 0; t < 256; t++) { excl[t] = run; run += cnt[t]; tot += ssum[t]; }
        excl[256] = run;
        g_nnz[row]  = run;
        g_invd[row] = rsqrtf(2.0f + tot);
    }
    __syncthreads();
    int off = excl[tid];
    for (int jj = 0; jj < 16; jj++) {
        int j = base + jj;
        float w = g_Ae[(size_t)row * N + j];
        if (j != row && w > 0.0f && w >= ti && w >= g_thr[j]) {
            g_cols[(size_t)row * N + off] = j;
            g_vals[(size_t)row * N + off] = w;
            off++;
        }
    }
}

__global__ void scale_kernel() {
    int row = blockIdx.x;
    int nn = g_nnz[row];
    float di = g_invd[row];
    for (int e = threadIdx.x; e < nn; e += 256) {
        size_t idx = (size_t)row * N + e;
        g_vals[idx] *= di * g_invd[g_cols[idx]];
    }
}

// ---------------- support GEMM: S = F(4096x1024) @ W(1024x1000) -------------
__global__ void __launch_bounds__(256) gemm_support(const float* __restrict__ A,
                                                    const float* __restrict__ B) {
    __shared__ float As[8][132];
    __shared__ float Bs[8][132];
    int row0 = blockIdx.y * 128, col0 = blockIdx.x * 128;
    int tid = threadIdx.x;
    int lrA = tid >> 1, lcA = (tid & 1) * 4;
    int lrB = tid >> 5, lcB = (tid & 31) * 4;
    int tx = tid & 15, ty = tid >> 4;
    float acc[8][8];
#pragma unroll
    for (int i = 0; i < 8; i++)
#pragma unroll
        for (int j = 0; j < 8; j++) acc[i][j] = 0.0f;

    const float* Aptr = A + (size_t)(row0 + lrA) * D + lcA;
    int bc = col0 + lcB;

    for (int k0 = 0; k0 < D; k0 += 8) {
        float4 av = *(const float4*)(Aptr + k0);
        As[lcA + 0][lrA] = av.x; As[lcA + 1][lrA] = av.y;
        As[lcA + 2][lrA] = av.z; As[lcA + 3][lrA] = av.w;
        float4 bv = make_float4(0.f, 0.f, 0.f, 0.f);
        if (bc < OUTD)
            bv = *(const float4*)(B + (size_t)(k0 + lrB) * OUTD + bc);
        *(float4*)&Bs[lrB][lcB] = bv;
        __syncthreads();
#pragma unroll
        for (int kk = 0; kk < 8; kk++) {
            float a[8], b[8];
            *(float4*)&a[0] = *(const float4*)&As[kk][ty * 8];
            *(float4*)&a[4] = *(const float4*)&As[kk][ty * 8 + 4];
            *(float4*)&b[0] = *(const float4*)&Bs[kk][tx * 8];
            *(float4*)&b[4] = *(const float4*)&Bs[kk][tx * 8 + 4];
#pragma unroll
            for (int i = 0; i < 8; i++)
#pragma unroll
                for (int j = 0; j < 8; j++) acc[i][j] += a[i] * b[j];
        }
        __syncthreads();
    }

#pragma unroll
    for (int i = 0; i < 8; i++) {
        int r = row0 + ty * 8 + i;
#pragma unroll
        for (int j = 0; j < 8; j++) {
            int c = col0 + tx * 8 + j;
            if (c < OUTD) g_S[(size_t)r * OUTD + c] = acc[i][j];
        }
    }
}

// ---------------- sparse propagation: An @ X ---------------------------------
template <int MODE>
__global__ void spmm_kernel(const float* __restrict__ bias,
                            const float* __restrict__ gamma,
                            const float* __restrict__ beta,
                            const float* __restrict__ mean,
                            const float* __restrict__ var,
                            float* __restrict__ out) {
    int row = blockIdx.x, tid = threadIdx.x;
    float di = g_invd[row];
    float diag = di * di;
    const float* X = (MODE == 0) ? g_S : g_t1;
    const float* Xrow = X + (size_t)row * OUTD;
    int n0 = tid, n1 = tid + 256, n2 = tid + 512, n3 = tid + 768;
    float a0 = diag * Xrow[n0];
    float a1 = diag * Xrow[n1];
    float a2 = diag * Xrow[n2];
    float a3 = (n3 < OUTD) ? diag * Xrow[n3] : 0.0f;

    int nn = g_nnz[row];
    for (int e = 0; e < nn; e++) {
        float v = g_vals[(size_t)row * N + e];
        const float* Xc = X + (size_t)g_cols[(size_t)row * N + e] * OUTD;
        a0 += v * Xc[n0];
        a1 += v * Xc[n1];
        a2 += v * Xc[n2];
        if (n3 < OUTD) a3 += v * Xc[n3];
    }

    if (MODE == 0) {
        float* T = g_t1 + (size_t)row * OUTD;
        T[n0] = a0; T[n1] = a1; T[n2] = a2;
        if (n3 < OUTD) T[n3] = a3;
    } else {
        float c0 = g_coef[0], c1 = g_coef[1], c2 = g_coef[2];
        const float* Srow = g_S + (size_t)row * OUTD;
        const float* Trow = g_t1 + (size_t)row * OUTD;
        float* Orow = out + (size_t)row * OUTD;
        int ns[4] = {n0, n1, n2, n3};
        float as[4] = {a0, a1, a2, a3};
#pragma unroll
        for (int r = 0; r < 4; r++) {
            int n = ns[r];
            if (n < OUTD) {
                float x = c0 * Srow[n] + c1 * Trow[n] + c2 * as[r] + bias[n];
                float y = (x - mean[n]) * rsqrtf(var[n] + BN_EPS) * gamma[n] + beta[n];
                Orow[n] = fmaxf(y, 0.0f);
            }
        }
    }
}

// ---------------- launch -----------------------------------------------------
extern "C" void kernel_launch(void* const* d_in, const int* in_sizes, int n_in,
                              void* d_out, int out_size) {
    const float* F     = (const float*)d_in[0];
    const float* W     = (const float*)d_in[1];
    const float* bias  = (const float*)d_in[2];
    const float* a1    = (const float*)d_in[3];
    const float* a2    = (const float*)d_in[4];
    const float* a3    = (const float*)d_in[5];
    const float* gamma = (const float*)d_in[6];
    const float* beta  = (const float*)d_in[7];
    const float* mean  = (const float*)d_in[8];
    const float* var   = (const float*)d_in[9];
    float* out = (float*)d_out;

    const int GRAM_SMEM = 128 * 133 * 4;   // 68096 B (> 4*TILE_B = 40960)
    static int configured = -1;
    if (configured < 0) {
        cudaFuncSetAttribute(gram_mma_kernel,
                             cudaFuncAttributeMaxDynamicSharedMemorySize, GRAM_SMEM);
        configured = 1;
    }

    aifa_kernel<<<1, 1>>>(a1, a2, a3);            // also zeroes g_sel_cnt
    sq_kernel<<<N, 256>>>(F);
    tobf16_kernel<<<N, 256>>>(F);
    gram_mma_kernel<<<528, 256, GRAM_SMEM>>>();
    count_kernel<<<N, 256>>>();
    select_kernel<<<N, 256>>>();                  // early-exits unused blocks
    build_kernel<<<N, 256>>>();
    scale_kernel<<<N, 256>>>();
    gemm_support<<<dim3(8, 32), 256>>>(F, W);
    spmm_kernel<0><<<N, 256>>>(bias, gamma, beta, mean, var, out);
    spmm_kernel<1><<<N, 256>>>(bias, gamma, beta, mean, var, out);
}

// round 5
// speedup vs baseline: 5.6333x; 1.9637x over previous
#include <cuda_runtime.h>
#include <cuda_bf16.h>
#include <math.h>
#include <stdint.h>

#define N 4096
#define D 1024
#define OUTD 1000
#define KSEL 819
#define BN_EPS 1e-5f

// ---------------- scratch (device globals; no allocations allowed) ----------
__device__ float g_sq[N];
__device__ __nv_bfloat16 g_Fbf[(size_t)N * D];   // bf16 hi of features
__device__ __nv_bfloat16 g_Flo[(size_t)N * D];   // bf16 lo residual
__device__ __nv_bfloat16 g_Wth[(size_t)1024 * 1024]; // W^T hi [n][k], n-padded
__device__ __nv_bfloat16 g_Wtl[(size_t)1024 * 1024]; // W^T lo
__device__ float g_Ae[(size_t)N * N];      // 64 MiB gaussian affinity
__device__ float g_thr[N];
__device__ float g_invd[N];
__device__ int   g_nnz[N];
__device__ int   g_poscnt[N];              // positives per Ae row (incl. diag)
__device__ int   g_cols[(size_t)N * N];
__device__ float g_vals[(size_t)N * N];
__device__ float g_S[(size_t)N * OUTD];
__device__ float g_t1[(size_t)N * OUTD];
__device__ float g_coef[3];
__device__ int   g_sel_cnt;
__device__ int   g_sel_rows[N];

// ---------------- baseline-PTX tensor-core helpers --------------------------
__device__ __forceinline__ uint32_t smem_u32(const void* p) {
    uint32_t a;
    asm("{ .reg .u64 t; cvta.to.shared.u64 t, %1; cvt.u32.u64 %0, t; }"
        : "=r"(a) : "l"(p));
    return a;
}
#define CP_ASYNC16(dst, src) \
    asm volatile("cp.async.cg.shared.global [%0], [%1], 16;" :: "r"(dst), "l"(src) : "memory")
#define CP_COMMIT() asm volatile("cp.async.commit_group;" ::: "memory")
#define CP_WAIT(n)  asm volatile("cp.async.wait_group %0;" :: "n"(n) : "memory")
#define LDMX4(r0, r1, r2, r3, addr) \
    asm volatile("ldmatrix.sync.aligned.m8n8.x4.shared.b16 {%0,%1,%2,%3}, [%4];" \
                 : "=r"(r0), "=r"(r1), "=r"(r2), "=r"(r3) : "r"(addr))
#define MMA16816(d, a, b0v, b1v) \
    asm volatile("mma.sync.aligned.m16n8k16.row.col.f32.bf16.bf16.f32 " \
                 "{%0,%1,%2,%3}, {%4,%5,%6,%7}, {%8,%9}, {%0,%1,%2,%3};" \
                 : "+f"((d)[0]), "+f"((d)[1]), "+f"((d)[2]), "+f"((d)[3]) \
                 : "r"((a)[0]), "r"((a)[1]), "r"((a)[2]), "r"((a)[3]), \
                   "r"(b0v), "r"(b1v))

// ---------------- tiny kernels ----------------------------------------------
__global__ void zero_kernel() {
    int i = blockIdx.x * 256 + threadIdx.x;
    if (i < N) g_poscnt[i] = 0;
    if (i == 0) g_sel_cnt = 0;
}

__global__ void aifa_kernel(const float* a1, const float* a2, const float* a3) {
    float x0 = a1[0], x1 = a2[0], x2 = a3[0];
    float m = fmaxf(x0, fmaxf(x1, x2));
    float e0 = expf(x0 - m), e1 = expf(x1 - m), e2 = expf(x2 - m);
    float s = e0 + e1 + e2;
    g_coef[0] = e0 / s; g_coef[1] = e1 / s; g_coef[2] = e2 / s;
}

// one pass over F: row sq-norms + bf16 hi/lo split
__global__ void prep_F(const float* __restrict__ F) {
    int row = blockIdx.x, tid = threadIdx.x;
    float4 v = *(const float4*)(F + (size_t)row * D + tid * 4);
    float s = v.x * v.x + v.y * v.y + v.z * v.z + v.w * v.w;

    __nv_bfloat16 h0 = __float2bfloat16(v.x), h1 = __float2bfloat16(v.y);
    __nv_bfloat16 h2 = __float2bfloat16(v.z), h3 = __float2bfloat16(v.w);
    __nv_bfloat162 ph0, ph1, pl0, pl1;
    ph0.x = h0; ph0.y = h1; ph1.x = h2; ph1.y = h3;
    pl0.x = __float2bfloat16(v.x - __bfloat162float(h0));
    pl0.y = __float2bfloat16(v.y - __bfloat162float(h1));
    pl1.x = __float2bfloat16(v.z - __bfloat162float(h2));
    pl1.y = __float2bfloat16(v.w - __bfloat162float(h3));
    size_t o = (size_t)row * D + tid * 4;
    *(__nv_bfloat162*)(g_Fbf + o)     = ph0;
    *(__nv_bfloat162*)(g_Fbf + o + 2) = ph1;
    *(__nv_bfloat162*)(g_Flo + o)     = pl0;
    *(__nv_bfloat162*)(g_Flo + o + 2) = pl1;

    __shared__ float red[256];
    red[tid] = s; __syncthreads();
    for (int o2 = 128; o2 > 0; o2 >>= 1) {
        if (tid < o2) red[tid] += red[tid + o2];
        __syncthreads();
    }
    if (tid == 0) g_sq[row] = red[0];
}

// transpose W [k=1024][n=1000] -> Wt hi/lo [n=1024 pad][k=1024]
__global__ void prep_W(const float* __restrict__ W) {
    __shared__ float t[32][33];
    int nx = blockIdx.x * 32 + threadIdx.x;       // n index (coalesced read)
#pragma unroll
    for (int s = 0; s < 4; s++) {
        int k = blockIdx.y * 32 + threadIdx.y + s * 8;
        t[threadIdx.y + s * 8][threadIdx.x] =
            (nx < OUTD) ? W[(size_t)k * OUTD + nx] : 0.0f;
    }
    __syncthreads();
#pragma unroll
    for (int s = 0; s < 4; s++) {
        int n_ = blockIdx.x * 32 + threadIdx.y + s * 8;
        int k_ = blockIdx.y * 32 + threadIdx.x;   // coalesced write
        float w = t[threadIdx.x][threadIdx.y + s * 8];
        __nv_bfloat16 hi = __float2bfloat16(w);
        g_Wth[(size_t)n_ * 1024 + k_] = hi;
        g_Wtl[(size_t)n_ * 1024 + k_] = __float2bfloat16(w - __bfloat162float(hi));
    }
}

// ---------------- mma.sync Gram: lower-tri 128x128 bf16 tiles ---------------
#define KC 32
#define NC (D / KC)
#define SAB 40
#define TILE_B (128 * SAB * 2)     // 10240 bytes per operand tile

__global__ void __launch_bounds__(256) gram_mma_kernel() {
    extern __shared__ char smem[];
    __shared__ int s_cr[128], s_cc[128];
    uint32_t sb = smem_u32(smem);
    int tid = threadIdx.x, wid = tid >> 5, lane = tid & 31;

    int bid = blockIdx.x;
    int tr = (int)((sqrtf(8.0f * (float)bid + 1.0f) - 1.0f) * 0.5f);
    while ((tr + 1) * (tr + 2) / 2 <= bid) tr++;
    while (tr * (tr + 1) / 2 > bid) tr--;
    int tc = bid - tr * (tr + 1) / 2;
    int row0 = tr * 128, col0 = tc * 128;

    const __nv_bfloat16* Ag = g_Fbf + (size_t)row0 * D;
    const __nv_bfloat16* Bg = g_Fbf + (size_t)col0 * D;

    float acc[2][8][4];
#pragma unroll
    for (int i = 0; i < 2; i++)
#pragma unroll
        for (int j = 0; j < 8; j++)
#pragma unroll
            for (int d = 0; d < 4; d++) acc[i][j][d] = 0.0f;

    int ldr = tid >> 2, lds = tid & 3;

    auto issue = [&](int c) {
        int s = c & 1;
        uint32_t dstA = sb + s * (2 * TILE_B);
        uint32_t dstB = dstA + TILE_B;
        int k0 = c * KC;
#pragma unroll
        for (int h = 0; h < 2; h++) {
            int r = ldr + h * 64;
            uint32_t off = (uint32_t)r * (SAB * 2) + lds * 16;
            CP_ASYNC16(dstA + off, (const void*)(Ag + (size_t)r * D + k0 + lds * 8));
            CP_ASYNC16(dstB + off, (const void*)(Bg + (size_t)r * D + k0 + lds * 8));
        }
    };

    int wm = wid & 3, wn = wid >> 2;
    int a_row = (lane & 7) + ((lane >> 3) & 1) * 8;
    int a_col = ((lane >> 4) & 1) * 8;
    int b_row = (lane & 7) + ((lane >> 4) & 1) * 8;
    int b_col = ((lane >> 3) & 1) * 8;

    issue(0); CP_COMMIT();
    for (int c = 0; c < NC; c++) {
        if (c + 1 < NC) { issue(c + 1); CP_COMMIT(); CP_WAIT(1); }
        else            { CP_WAIT(0); }
        __syncthreads();

        int s = c & 1;
        uint32_t Abase = sb + s * (2 * TILE_B) + (uint32_t)(wm * 32) * (SAB * 2);
        uint32_t Bbase = sb + s * (2 * TILE_B) + TILE_B + (uint32_t)(wn * 64) * (SAB * 2);

        uint32_t a[2][2][4];
#pragma unroll
        for (int i = 0; i < 2; i++)
#pragma unroll
            for (int st = 0; st < 2; st++) {
                uint32_t ad = Abase + (uint32_t)(i * 16 + a_row) * (SAB * 2)
                            + (uint32_t)(st * 16 + a_col) * 2;
                LDMX4(a[i][st][0], a[i][st][1], a[i][st][2], a[i][st][3], ad);
            }
        uint32_t b[4][2][4];
#pragma unroll
        for (int jp = 0; jp < 4; jp++)
#pragma unroll
            for (int st = 0; st < 2; st++) {
                uint32_t bd = Bbase + (uint32_t)(jp * 16 + b_row) * (SAB * 2)
                            + (uint32_t)(st * 16 + b_col) * 2;
                LDMX4(b[jp][st][0], b[jp][st][1], b[jp][st][2], b[jp][st][3], bd);
            }
#pragma unroll
        for (int i = 0; i < 2; i++)
#pragma unroll
            for (int j = 0; j < 8; j++) {
                int jp = j >> 1, hf = (j & 1) * 2;
#pragma unroll
                for (int st = 0; st < 2; st++)
                    MMA16816(acc[i][j], a[i][st], b[jp][st][hf], b[jp][st][hf + 1]);
            }
        __syncthreads();
    }

    if (tid < 128) { s_cr[tid] = 0; s_cc[tid] = 0; }
    __syncthreads();

    // epilogue: exp into smem [128][133] + positive counts
    float* epi = (float*)smem;
    int er = lane >> 2, ec = (lane & 3) * 2;
#pragma unroll
    for (int i = 0; i < 2; i++)
#pragma unroll
        for (int j = 0; j < 8; j++)
#pragma unroll
            for (int d = 0; d < 4; d++) {
                int r = wm * 32 + i * 16 + (d >> 1) * 8 + er;
                int cc = wn * 64 + j * 8 + ec + (d & 1);
                float d2 = fmaxf(g_sq[row0 + r] + g_sq[col0 + cc] - 2.0f * acc[i][j][d], 0.0f);
                float e = expf(-d2 / 9.0f);
                epi[r * 133 + cc] = e;
                if (e > 0.0f) {
                    atomicAdd(&s_cr[r], 1);
                    if (tr != tc) atomicAdd(&s_cc[cc], 1);
                }
            }
    __syncthreads();

    for (int rr = wid * 16; rr < wid * 16 + 16; rr++) {
        float4 v;
        v.x = epi[rr * 133 + lane * 4 + 0];
        v.y = epi[rr * 133 + lane * 4 + 1];
        v.z = epi[rr * 133 + lane * 4 + 2];
        v.w = epi[rr * 133 + lane * 4 + 3];
        *(float4*)(g_Ae + (size_t)(row0 + rr) * N + col0 + lane * 4) = v;
    }
    for (int cc = wid * 16; cc < wid * 16 + 16; cc++) {
        float4 v;
        v.x = epi[(lane * 4 + 0) * 133 + cc];
        v.y = epi[(lane * 4 + 1) * 133 + cc];
        v.z = epi[(lane * 4 + 2) * 133 + cc];
        v.w = epi[(lane * 4 + 3) * 133 + cc];
        *(float4*)(g_Ae + (size_t)(col0 + cc) * N + row0 + lane * 4) = v;
    }
    if (tid < 128) {
        atomicAdd(&g_poscnt[row0 + tid], s_cr[tid]);
        if (tr != tc) atomicAdd(&g_poscnt[col0 + tid], s_cc[tid]);
    }
}

// ---------------- threshold dispatch from fused counts ----------------------
__global__ void thr_kernel() {
    int row = blockIdx.x * 256 + threadIdx.x;
    if (row >= N) return;
    if (g_poscnt[row] < KSEL) {
        g_thr[row] = 0.0f;                 // K-th largest is a zero
    } else {
        int idx = atomicAdd(&g_sel_cnt, 1);
        g_sel_rows[idx] = row;
    }
}

// ---------------- full radix select (only rows with >= K positives) ---------
__global__ void select_kernel() {
    __shared__ unsigned v[N];
    __shared__ int hist[256];
    __shared__ int sfx[256];
    __shared__ int s_bin, s_rem;
    if (blockIdx.x >= g_sel_cnt) return;
    int row = g_sel_rows[blockIdx.x];
    int tid = threadIdx.x, lane = tid & 31;
    for (int i = tid; i < N; i += 256)
        v[i] = __float_as_uint(g_Ae[(size_t)row * N + i]);
    __syncthreads();

    unsigned prefix = 0;
    int remaining = KSEL;
    for (int shift = 24; shift >= 0; shift -= 8) {
        hist[tid] = 0;
        __syncthreads();
        unsigned hm = (shift == 24) ? 0u : (0xFFFFFFFFu << (shift + 8));
        unsigned ph = prefix & hm;
#pragma unroll
        for (int i = tid; i < N; i += 256) {
            unsigned x = v[i];
            bool act = ((x & hm) == ph);
            int bin = (x >> shift) & 255;
            unsigned key = act ? (unsigned)bin : 0xFFFFFFFFu;
            unsigned mask = __match_any_sync(0xFFFFFFFFu, key);
            if (act && ((__ffs(mask) - 1) == lane))
                atomicAdd(&hist[bin], __popc(mask));
        }
        __syncthreads();
        sfx[tid] = hist[tid];
        __syncthreads();
        for (int off = 1; off < 256; off <<= 1) {
            int val = (tid + off < 256) ? sfx[tid + off] : 0;
            __syncthreads();
            sfx[tid] += val;
            __syncthreads();
        }
        int nb = (tid < 255) ? sfx[tid + 1] : 0;
        if (sfx[tid] >= remaining && nb < remaining) {
            s_bin = tid;
            s_rem = remaining - nb;
        }
        __syncthreads();
        prefix |= ((unsigned)s_bin) << shift;
        remaining = s_rem;
        __syncthreads();
    }
    if (tid == 0) g_thr[row] = __uint_as_float(prefix);
}

// ---------------- build sparse A (raw Ae vals), degrees ---------------------
__global__ void build_kernel() {
    int row = blockIdx.x, tid = threadIdx.x;
    // fast path: only diagonal positive -> no off-diag entries can survive
    if (g_poscnt[row] == 1) {
        if (tid == 0) { g_nnz[row] = 0; g_invd[row] = rsqrtf(2.0f); }
        return;
    }
    float ti = g_thr[row];
    __shared__ int   cnt[256];
    __shared__ float ssum[256];
    __shared__ int   excl[257];
    int base = tid * 16;
    int lc = 0; float ls = 0.0f;
    for (int jj = 0; jj < 16; jj++) {
        int j = base + jj;
        float w = g_Ae[(size_t)row * N + j];
        if (j != row && w > 0.0f && w >= ti && w >= g_thr[j]) { lc++; ls += w; }
    }
    cnt[tid] = lc; ssum[tid] = ls;
    __syncthreads();
    if (tid == 0) {
        int run = 0; float tot = 0.0f;
        for (int t = 0; t < 256; t++) { excl[t] = run; run += cnt[t]; tot += ssum[t]; }
        excl[256] = run;
        g_nnz[row]  = run;
        g_invd[row] = rsqrtf(2.0f + tot);
    }
    __syncthreads();
    int off = excl[tid];
    for (int jj = 0; jj < 16; jj++) {
        int j = base + jj;
        float w = g_Ae[(size_t)row * N + j];
        if (j != row && w > 0.0f && w >= ti && w >= g_thr[j]) {
            g_cols[(size_t)row * N + off] = j;
            g_vals[(size_t)row * N + off] = w;
            off++;
        }
    }
}

__global__ void scale_kernel() {
    int row = blockIdx.x;
    int nn = g_nnz[row];
    float di = g_invd[row];
    for (int e = threadIdx.x; e < nn; e += 256) {
        size_t idx = (size_t)row * N + e;
        g_vals[idx] *= di * g_invd[g_cols[idx]];
    }
}

// ---------------- support GEMM via mma.sync, bf16 split-2 -------------------
// S = F @ W with F = Fhi+Flo, W = Whi+Wlo: acc = Fhi*Whi + Flo*Whi + Fhi*Wlo.
#define NCK (D / KC)
#define STAGE_B (4 * TILE_B)

__global__ void __launch_bounds__(256) support_mma_kernel() {
    extern __shared__ char smem[];
    uint32_t sb = smem_u32(smem);
    int tid = threadIdx.x, wid = tid >> 5, lane = tid & 31;
    int row0 = blockIdx.y * 128, col0 = blockIdx.x * 128;

    float acc[2][8][4];
#pragma unroll
    for (int i = 0; i < 2; i++)
#pragma unroll
        for (int j = 0; j < 8; j++)
#pragma unroll
            for (int d = 0; d < 4; d++) acc[i][j][d] = 0.0f;

    int ldr = tid >> 2, lds = tid & 3;

    auto issue = [&](int c) {
        int s = c & 1;
        uint32_t st = sb + s * STAGE_B;
        int k0 = c * KC;
#pragma unroll
        for (int h = 0; h < 2; h++) {
            int r = ldr + h * 64;
            uint32_t off = (uint32_t)r * (SAB * 2) + lds * 16;
            CP_ASYNC16(st + off,              (const void*)(g_Fbf + (size_t)(row0 + r) * D + k0 + lds * 8));
            CP_ASYNC16(st + TILE_B + off,     (const void*)(g_Flo + (size_t)(row0 + r) * D + k0 + lds * 8));
            CP_ASYNC16(st + 2 * TILE_B + off, (const void*)(g_Wth + (size_t)(col0 + r) * 1024 + k0 + lds * 8));
            CP_ASYNC16(st + 3 * TILE_B + off, (const void*)(g_Wtl + (size_t)(col0 + r) * 1024 + k0 + lds * 8));
        }
    };

    int wm = wid & 3, wn = wid >> 2;
    int a_row = (lane & 7) + ((lane >> 3) & 1) * 8;
    int a_col = ((lane >> 4) & 1) * 8;
    int b_row = (lane & 7) + ((lane >> 4) & 1) * 8;
    int b_col = ((lane >> 3) & 1) * 8;

    issue(0); CP_COMMIT();
    for (int c = 0; c < NCK; c++) {
        if (c + 1 < NCK) { issue(c + 1); CP_COMMIT(); CP_WAIT(1); }
        else             { CP_WAIT(0); }
        __syncthreads();

        int s = c & 1;
        uint32_t Ahb = sb + s * STAGE_B + (uint32_t)(wm * 32) * (SAB * 2);
        uint32_t Alb = Ahb + TILE_B;
        uint32_t Bhb = sb + s * STAGE_B + 2 * TILE_B + (uint32_t)(wn * 64) * (SAB * 2);
        uint32_t Blb = Bhb + TILE_B;

        uint32_t ah[2][2][4], al[2][2][4];
#pragma unroll
        for (int i = 0; i < 2; i++)
#pragma unroll
            for (int st = 0; st < 2; st++) {
                uint32_t ro = (uint32_t)(i * 16 + a_row) * (SAB * 2)
                            + (uint32_t)(st * 16 + a_col) * 2;
                LDMX4(ah[i][st][0], ah[i][st][1], ah[i][st][2], ah[i][st][3], Ahb + ro);
                LDMX4(al[i][st][0], al[i][st][1], al[i][st][2], al[i][st][3], Alb + ro);
            }
#pragma unroll
        for (int jp = 0; jp < 4; jp++)
#pragma unroll
            for (int st = 0; st < 2; st++) {
                uint32_t ro = (uint32_t)(jp * 16 + b_row) * (SAB * 2)
                            + (uint32_t)(st * 16 + b_col) * 2;
                uint32_t bh[4], bl[4];
                LDMX4(bh[0], bh[1], bh[2], bh[3], Bhb + ro);
                LDMX4(bl[0], bl[1], bl[2], bl[3], Blb + ro);
#pragma unroll
                for (int i = 0; i < 2; i++)
#pragma unroll
                    for (int jh = 0; jh < 2; jh++) {
                        int j = jp * 2 + jh, hf = jh * 2;
                        MMA16816(acc[i][j], ah[i][st], bh[hf], bh[hf + 1]);
                        MMA16816(acc[i][j], al[i][st], bh[hf], bh[hf + 1]);
                        MMA16816(acc[i][j], ah[i][st], bl[hf], bl[hf + 1]);
                    }
            }
        __syncthreads();
    }

    int er = lane >> 2, ec = (lane & 3) * 2;
#pragma unroll
    for (int i = 0; i < 2; i++)
#pragma unroll
        for (int j = 0; j < 8; j++)
#pragma unroll
            for (int dp = 0; dp < 2; dp++) {
                int r = row0 + wm * 32 + i * 16 + dp * 8 + er;
                int c = col0 + wn * 64 + j * 8 + ec;
                if (c < OUTD) {
                    float2 v = make_float2(acc[i][j][dp * 2], acc[i][j][dp * 2 + 1]);
                    *(float2*)(g_S + (size_t)r * OUTD + c) = v;
                }
            }
}

// ---------------- sparse propagation: An @ X ---------------------------------
template <int MODE>
__global__ void spmm_kernel(const float* __restrict__ bias,
                            const float* __restrict__ gamma,
                            const float* __restrict__ beta,
                            const float* __restrict__ mean,
                            const float* __restrict__ var,
                            float* __restrict__ out) {
    int row = blockIdx.x, tid = threadIdx.x;
    float di = g_invd[row];
    float diag = di * di;
    const float* X = (MODE == 0) ? g_S : g_t1;
    const float* Xrow = X + (size_t)row * OUTD;
    int n0 = tid, n1 = tid + 256, n2 = tid + 512, n3 = tid + 768;
    float a0 = diag * Xrow[n0];
    float a1 = diag * Xrow[n1];
    float a2 = diag * Xrow[n2];
    float a3 = (n3 < OUTD) ? diag * Xrow[n3] : 0.0f;

    int nn = g_nnz[row];
    for (int e = 0; e < nn; e++) {
        float v = g_vals[(size_t)row * N + e];
        const float* Xc = X + (size_t)g_cols[(size_t)row * N + e] * OUTD;
        a0 += v * Xc[n0];
        a1 += v * Xc[n1];
        a2 += v * Xc[n2];
        if (n3 < OUTD) a3 += v * Xc[n3];
    }

    if (MODE == 0) {
        float* T = g_t1 + (size_t)row * OUTD;
        T[n0] = a0; T[n1] = a1; T[n2] = a2;
        if (n3 < OUTD) T[n3] = a3;
    } else {
        float c0 = g_coef[0], c1 = g_coef[1], c2 = g_coef[2];
        const float* Srow = g_S + (size_t)row * OUTD;
        const float* Trow = g_t1 + (size_t)row * OUTD;
        float* Orow = out + (size_t)row * OUTD;
        int ns[4] = {n0, n1, n2, n3};
        float as[4] = {a0, a1, a2, a3};
#pragma unroll
        for (int r = 0; r < 4; r++) {
            int n = ns[r];
            if (n < OUTD) {
                float x = c0 * Srow[n] + c1 * Trow[n] + c2 * as[r] + bias[n];
                float y = (x - mean[n]) * rsqrtf(var[n] + BN_EPS) * gamma[n] + beta[n];
                Orow[n] = fmaxf(y, 0.0f);
            }
        }
    }
}

// ---------------- launch -----------------------------------------------------
extern "C" void kernel_launch(void* const* d_in, const int* in_sizes, int n_in,
                              void* d_out, int out_size) {
    const float* F     = (const float*)d_in[0];
    const float* W     = (const float*)d_in[1];
    const float* bias  = (const float*)d_in[2];
    const float* a1    = (const float*)d_in[3];
    const float* a2    = (const float*)d_in[4];
    const float* a3    = (const float*)d_in[5];
    const float* gamma = (const float*)d_in[6];
    const float* beta  = (const float*)d_in[7];
    const float* mean  = (const float*)d_in[8];
    const float* var   = (const float*)d_in[9];
    float* out = (float*)d_out;

    const int GRAM_SMEM = 128 * 133 * 4;     // 68096 B (>= 4*TILE_B mainloop)
    const int SUP_SMEM  = 2 * STAGE_B;       // 81920 B
    static int configured = -1;
    if (configured < 0) {
        cudaFuncSetAttribute(gram_mma_kernel,
                             cudaFuncAttributeMaxDynamicSharedMemorySize, GRAM_SMEM);
        cudaFuncSetAttribute(support_mma_kernel,
                             cudaFuncAttributeMaxDynamicSharedMemorySize, SUP_SMEM);
        configured = 1;
    }

    zero_kernel<<<16, 256>>>();
    aifa_kernel<<<1, 1>>>(a1, a2, a3);
    prep_F<<<N, 256>>>(F);
    prep_W<<<dim3(32, 32), dim3(32, 8)>>>(W);
    gram_mma_kernel<<<528, 256, GRAM_SMEM>>>();
    support_mma_kernel<<<dim3(8, 32), 256, SUP_SMEM>>>();
    thr_kernel<<<16, 256>>>();
    select_kernel<<<N, 256>>>();
    build_kernel<<<N, 256>>>();
    scale_kernel<<<N, 256>>>();
    spmm_kernel<0><<<N, 256>>>(bias, gamma, beta, mean, var, out);
    spmm_kernel<1><<<N, 256>>>(bias, gamma, beta, mean, var, out);
}

// round 6
// speedup vs baseline: 5.7722x; 1.0247x over previous
#include <cuda_runtime.h>
#include <cuda_bf16.h>
#include <math.h>
#include <stdint.h>

#define N 4096
#define D 1024
#define OUTD 1000
#define KSEL 819
#define BN_EPS 1e-5f

// ---------------- scratch (device globals; no allocations allowed) ----------
__device__ float g_sq[N];
__device__ __nv_bfloat16 g_Fbf[(size_t)N * D];   // bf16 hi of features
__device__ __nv_bfloat16 g_Flo[(size_t)N * D];   // bf16 lo residual
__device__ __nv_bfloat16 g_Wth[(size_t)1024 * 1024]; // W^T hi [n][k], n-padded
__device__ __nv_bfloat16 g_Wtl[(size_t)1024 * 1024]; // W^T lo
__device__ float g_Ae[(size_t)N * N];      // 64 MiB gaussian affinity
__device__ float g_thr[N];
__device__ float g_invd[N];
__device__ int   g_nnz[N];
__device__ int   g_poscnt[N];              // positives per Ae row (incl. diag)
__device__ int   g_cols[(size_t)N * N];
__device__ float g_vals[(size_t)N * N];
__device__ float g_S[(size_t)N * OUTD];
__device__ float g_t1[(size_t)N * OUTD];
__device__ float g_coef[3];
__device__ int   g_sel_cnt;
__device__ int   g_sel_rows[N];

// ---------------- baseline-PTX tensor-core helpers --------------------------
__device__ __forceinline__ uint32_t smem_u32(const void* p) {
    uint32_t a;
    asm("{ .reg .u64 t; cvta.to.shared.u64 t, %1; cvt.u32.u64 %0, t; }"
        : "=r"(a) : "l"(p));
    return a;
}
#define CP_ASYNC16(dst, src) \
    asm volatile("cp.async.cg.shared.global [%0], [%1], 16;" :: "r"(dst), "l"(src) : "memory")
#define CP_COMMIT() asm volatile("cp.async.commit_group;" ::: "memory")
#define CP_WAIT(n)  asm volatile("cp.async.wait_group %0;" :: "n"(n) : "memory")
#define LDMX4(r0, r1, r2, r3, addr) \
    asm volatile("ldmatrix.sync.aligned.m8n8.x4.shared.b16 {%0,%1,%2,%3}, [%4];" \
                 : "=r"(r0), "=r"(r1), "=r"(r2), "=r"(r3) : "r"(addr))
#define MMA16816(d, a, b0v, b1v) \
    asm volatile("mma.sync.aligned.m16n8k16.row.col.f32.bf16.bf16.f32 " \
                 "{%0,%1,%2,%3}, {%4,%5,%6,%7}, {%8,%9}, {%0,%1,%2,%3};" \
                 : "+f"((d)[0]), "+f"((d)[1]), "+f"((d)[2]), "+f"((d)[3]) \
                 : "r"((a)[0]), "r"((a)[1]), "r"((a)[2]), "r"((a)[3]), \
                   "r"(b0v), "r"(b1v))

// expf(-d2/9) with exact-zero fast path: for d2 >= 1000, -d2/9 < -111 and
// expf underflows to exactly 0.0f, so skipping the evaluation is bit-exact.
#define D2_ZERO_CUT 1000.0f

// ---------------- tiny kernels ----------------------------------------------
__global__ void init_kernel(const float* a1, const float* a2, const float* a3) {
    int i = blockIdx.x * 256 + threadIdx.x;
    if (i < N) g_poscnt[i] = 0;
    if (i == 0) {
        g_sel_cnt = 0;
        float x0 = a1[0], x1 = a2[0], x2 = a3[0];
        float m = fmaxf(x0, fmaxf(x1, x2));
        float e0 = expf(x0 - m), e1 = expf(x1 - m), e2 = expf(x2 - m);
        float s = e0 + e1 + e2;
        g_coef[0] = e0 / s; g_coef[1] = e1 / s; g_coef[2] = e2 / s;
    }
}

// one pass over F: row sq-norms + bf16 hi/lo split
__global__ void prep_F(const float* __restrict__ F) {
    int row = blockIdx.x, tid = threadIdx.x;
    float4 v = *(const float4*)(F + (size_t)row * D + tid * 4);
    float s = v.x * v.x + v.y * v.y + v.z * v.z + v.w * v.w;

    __nv_bfloat16 h0 = __float2bfloat16(v.x), h1 = __float2bfloat16(v.y);
    __nv_bfloat16 h2 = __float2bfloat16(v.z), h3 = __float2bfloat16(v.w);
    __nv_bfloat162 ph0, ph1, pl0, pl1;
    ph0.x = h0; ph0.y = h1; ph1.x = h2; ph1.y = h3;
    pl0.x = __float2bfloat16(v.x - __bfloat162float(h0));
    pl0.y = __float2bfloat16(v.y - __bfloat162float(h1));
    pl1.x = __float2bfloat16(v.z - __bfloat162float(h2));
    pl1.y = __float2bfloat16(v.w - __bfloat162float(h3));
    size_t o = (size_t)row * D + tid * 4;
    *(__nv_bfloat162*)(g_Fbf + o)     = ph0;
    *(__nv_bfloat162*)(g_Fbf + o + 2) = ph1;
    *(__nv_bfloat162*)(g_Flo + o)     = pl0;
    *(__nv_bfloat162*)(g_Flo + o + 2) = pl1;

    __shared__ float red[256];
    red[tid] = s; __syncthreads();
    for (int o2 = 128; o2 > 0; o2 >>= 1) {
        if (tid < o2) red[tid] += red[tid + o2];
        __syncthreads();
    }
    if (tid == 0) g_sq[row] = red[0];
}

// transpose W [k=1024][n=1000] -> Wt hi/lo [n=1024 pad][k=1024]
__global__ void prep_W(const float* __restrict__ W) {
    __shared__ float t[32][33];
    int nx = blockIdx.x * 32 + threadIdx.x;       // n index (coalesced read)
#pragma unroll
    for (int s = 0; s < 4; s++) {
        int k = blockIdx.y * 32 + threadIdx.y + s * 8;
        t[threadIdx.y + s * 8][threadIdx.x] =
            (nx < OUTD) ? W[(size_t)k * OUTD + nx] : 0.0f;
    }
    __syncthreads();
#pragma unroll
    for (int s = 0; s < 4; s++) {
        int n_ = blockIdx.x * 32 + threadIdx.y + s * 8;
        int k_ = blockIdx.y * 32 + threadIdx.x;   // coalesced write
        float w = t[threadIdx.x][threadIdx.y + s * 8];
        __nv_bfloat16 hi = __float2bfloat16(w);
        g_Wth[(size_t)n_ * 1024 + k_] = hi;
        g_Wtl[(size_t)n_ * 1024 + k_] = __float2bfloat16(w - __bfloat162float(hi));
    }
}

// ---------------- mma.sync Gram: lower-tri 128x128 bf16 tiles ---------------
#define KC 32
#define NC (D / KC)
#define SAB 40
#define TILE_B (128 * SAB * 2)     // 10240 bytes per operand tile

__global__ void __launch_bounds__(256) gram_mma_kernel() {
    extern __shared__ char smem[];
    __shared__ int s_cr[128], s_cc[128];
    uint32_t sb = smem_u32(smem);
    int tid = threadIdx.x, wid = tid >> 5, lane = tid & 31;

    int bid = blockIdx.x;
    int tr = (int)((sqrtf(8.0f * (float)bid + 1.0f) - 1.0f) * 0.5f);
    while ((tr + 1) * (tr + 2) / 2 <= bid) tr++;
    while (tr * (tr + 1) / 2 > bid) tr--;
    int tc = bid - tr * (tr + 1) / 2;
    int row0 = tr * 128, col0 = tc * 128;

    const __nv_bfloat16* Ag = g_Fbf + (size_t)row0 * D;
    const __nv_bfloat16* Bg = g_Fbf + (size_t)col0 * D;

    float acc[2][8][4];
#pragma unroll
    for (int i = 0; i < 2; i++)
#pragma unroll
        for (int j = 0; j < 8; j++)
#pragma unroll
            for (int d = 0; d < 4; d++) acc[i][j][d] = 0.0f;

    int ldr = tid >> 2, lds = tid & 3;

    auto issue = [&](int c) {
        int s = c & 1;
        uint32_t dstA = sb + s * (2 * TILE_B);
        uint32_t dstB = dstA + TILE_B;
        int k0 = c * KC;
#pragma unroll
        for (int h = 0; h < 2; h++) {
            int r = ldr + h * 64;
            uint32_t off = (uint32_t)r * (SAB * 2) + lds * 16;
            CP_ASYNC16(dstA + off, (const void*)(Ag + (size_t)r * D + k0 + lds * 8));
            CP_ASYNC16(dstB + off, (const void*)(Bg + (size_t)r * D + k0 + lds * 8));
        }
    };

    int wm = wid & 3, wn = wid >> 2;
    int a_row = (lane & 7) + ((lane >> 3) & 1) * 8;
    int a_col = ((lane >> 4) & 1) * 8;
    int b_row = (lane & 7) + ((lane >> 4) & 1) * 8;
    int b_col = ((lane >> 3) & 1) * 8;

    issue(0); CP_COMMIT();
    for (int c = 0; c < NC; c++) {
        if (c + 1 < NC) { issue(c + 1); CP_COMMIT(); CP_WAIT(1); }
        else            { CP_WAIT(0); }
        __syncthreads();

        int s = c & 1;
        uint32_t Abase = sb + s * (2 * TILE_B) + (uint32_t)(wm * 32) * (SAB * 2);
        uint32_t Bbase = sb + s * (2 * TILE_B) + TILE_B + (uint32_t)(wn * 64) * (SAB * 2);

        uint32_t a[2][2][4];
#pragma unroll
        for (int i = 0; i < 2; i++)
#pragma unroll
            for (int st = 0; st < 2; st++) {
                uint32_t ad = Abase + (uint32_t)(i * 16 + a_row) * (SAB * 2)
                            + (uint32_t)(st * 16 + a_col) * 2;
                LDMX4(a[i][st][0], a[i][st][1], a[i][st][2], a[i][st][3], ad);
            }
        uint32_t b[4][2][4];
#pragma unroll
        for (int jp = 0; jp < 4; jp++)
#pragma unroll
            for (int st = 0; st < 2; st++) {
                uint32_t bd = Bbase + (uint32_t)(jp * 16 + b_row) * (SAB * 2)
                            + (uint32_t)(st * 16 + b_col) * 2;
                LDMX4(b[jp][st][0], b[jp][st][1], b[jp][st][2], b[jp][st][3], bd);
            }
#pragma unroll
        for (int i = 0; i < 2; i++)
#pragma unroll
            for (int j = 0; j < 8; j++) {
                int jp = j >> 1, hf = (j & 1) * 2;
#pragma unroll
                for (int st = 0; st < 2; st++)
                    MMA16816(acc[i][j], a[i][st], b[jp][st][hf], b[jp][st][hf + 1]);
            }
        __syncthreads();
    }

    if (tid < 128) { s_cr[tid] = 0; s_cc[tid] = 0; }
    __syncthreads();

    // epilogue: exp (with exact-zero skip) into smem [128][133] + counts
    float* epi = (float*)smem;
    int er = lane >> 2, ec = (lane & 3) * 2;
#pragma unroll
    for (int i = 0; i < 2; i++)
#pragma unroll
        for (int j = 0; j < 8; j++)
#pragma unroll
            for (int d = 0; d < 4; d++) {
                int r = wm * 32 + i * 16 + (d >> 1) * 8 + er;
                int cc = wn * 64 + j * 8 + ec + (d & 1);
                float d2 = fmaxf(g_sq[row0 + r] + g_sq[col0 + cc] - 2.0f * acc[i][j][d], 0.0f);
                float e = 0.0f;
                if (d2 < D2_ZERO_CUT) {            // warp-uniformly rare
                    e = expf(-d2 / 9.0f);
                    if (e > 0.0f) {
                        atomicAdd(&s_cr[r], 1);
                        if (tr != tc) atomicAdd(&s_cc[cc], 1);
                    }
                }
                epi[r * 133 + cc] = e;
            }
    __syncthreads();

    for (int rr = wid * 16; rr < wid * 16 + 16; rr++) {
        float4 v;
        v.x = epi[rr * 133 + lane * 4 + 0];
        v.y = epi[rr * 133 + lane * 4 + 1];
        v.z = epi[rr * 133 + lane * 4 + 2];
        v.w = epi[rr * 133 + lane * 4 + 3];
        *(float4*)(g_Ae + (size_t)(row0 + rr) * N + col0 + lane * 4) = v;
    }
    for (int cc = wid * 16; cc < wid * 16 + 16; cc++) {
        float4 v;
        v.x = epi[(lane * 4 + 0) * 133 + cc];
        v.y = epi[(lane * 4 + 1) * 133 + cc];
        v.z = epi[(lane * 4 + 2) * 133 + cc];
        v.w = epi[(lane * 4 + 3) * 133 + cc];
        *(float4*)(g_Ae + (size_t)(col0 + cc) * N + row0 + lane * 4) = v;
    }
    if (tid < 128) {
        if (s_cr[tid]) atomicAdd(&g_poscnt[row0 + tid], s_cr[tid]);
        if (tr != tc && s_cc[tid]) atomicAdd(&g_poscnt[col0 + tid], s_cc[tid]);
    }
}

// ---------------- threshold dispatch from fused counts ----------------------
__global__ void thr_kernel() {
    int row = blockIdx.x * 256 + threadIdx.x;
    if (row >= N) return;
    if (g_poscnt[row] < KSEL) {
        g_thr[row] = 0.0f;                 // K-th largest is a zero
    } else {
        int idx = atomicAdd(&g_sel_cnt, 1);
        g_sel_rows[idx] = row;
    }
}

// ---------------- full radix select (only rows with >= K positives) ---------
__global__ void select_kernel() {
    __shared__ unsigned v[N];
    __shared__ int hist[256];
    __shared__ int sfx[256];
    __shared__ int s_bin, s_rem;
    if (blockIdx.x >= g_sel_cnt) return;
    int row = g_sel_rows[blockIdx.x];
    int tid = threadIdx.x, lane = tid & 31;
    for (int i = tid; i < N; i += 256)
        v[i] = __float_as_uint(g_Ae[(size_t)row * N + i]);
    __syncthreads();

    unsigned prefix = 0;
    int remaining = KSEL;
    for (int shift = 24; shift >= 0; shift -= 8) {
        hist[tid] = 0;
        __syncthreads();
        unsigned hm = (shift == 24) ? 0u : (0xFFFFFFFFu << (shift + 8));
        unsigned ph = prefix & hm;
#pragma unroll
        for (int i = tid; i < N; i += 256) {
            unsigned x = v[i];
            bool act = ((x & hm) == ph);
            int bin = (x >> shift) & 255;
            unsigned key = act ? (unsigned)bin : 0xFFFFFFFFu;
            unsigned mask = __match_any_sync(0xFFFFFFFFu, key);
            if (act && ((__ffs(mask) - 1) == lane))
                atomicAdd(&hist[bin], __popc(mask));
        }
        __syncthreads();
        sfx[tid] = hist[tid];
        __syncthreads();
        for (int off = 1; off < 256; off <<= 1) {
            int val = (tid + off < 256) ? sfx[tid + off] : 0;
            __syncthreads();
            sfx[tid] += val;
            __syncthreads();
        }
        int nb = (tid < 255) ? sfx[tid + 1] : 0;
        if (sfx[tid] >= remaining && nb < remaining) {
            s_bin = tid;
            s_rem = remaining - nb;
        }
        __syncthreads();
        prefix |= ((unsigned)s_bin) << shift;
        remaining = s_rem;
        __syncthreads();
    }
    if (tid == 0) g_thr[row] = __uint_as_float(prefix);
}

// ---------------- build sparse A (raw Ae vals), degrees ---------------------
__global__ void build_kernel() {
    int row = blockIdx.x, tid = threadIdx.x;
    if (g_poscnt[row] == 1) {   // only diagonal positive
        if (tid == 0) { g_nnz[row] = 0; g_invd[row] = rsqrtf(2.0f); }
        return;
    }
    float ti = g_thr[row];
    __shared__ int   cnt[256];
    __shared__ float ssum[256];
    __shared__ int   excl[257];
    int base = tid * 16;
    int lc = 0; float ls = 0.0f;
    for (int jj = 0; jj < 16; jj++) {
        int j = base + jj;
        float w = g_Ae[(size_t)row * N + j];
        if (j != row && w > 0.0f && w >= ti && w >= g_thr[j]) { lc++; ls += w; }
    }
    cnt[tid] = lc; ssum[tid] = ls;
    __syncthreads();
    if (tid == 0) {
        int run = 0; float tot = 0.0f;
        for (int t = 0; t < 256; t++) { excl[t] = run; run += cnt[t]; tot += ssum[t]; }
        excl[256] = run;
        g_nnz[row]  = run;
        g_invd[row] = rsqrtf(2.0f + tot);
    }
    __syncthreads();
    int off = excl[tid];
    for (int jj = 0; jj < 16; jj++) {
        int j = base + jj;
        float w = g_Ae[(size_t)row * N + j];
        if (j != row && w > 0.0f && w >= ti && w >= g_thr[j]) {
            g_cols[(size_t)row * N + off] = j;
            g_vals[(size_t)row * N + off] = w;
            off++;
        }
    }
}

__global__ void scale_kernel() {
    int row = blockIdx.x;
    int nn = g_nnz[row];
    float di = g_invd[row];
    for (int e = threadIdx.x; e < nn; e += 256) {
        size_t idx = (size_t)row * N + e;
        g_vals[idx] *= di * g_invd[g_cols[idx]];
    }
}

// ---------------- support GEMM via mma.sync, bf16 split-2 -------------------
#define NCK (D / KC)
#define STAGE_B (4 * TILE_B)

__global__ void __launch_bounds__(256) support_mma_kernel() {
    extern __shared__ char smem[];
    uint32_t sb = smem_u32(smem);
    int tid = threadIdx.x, wid = tid >> 5, lane = tid & 31;
    int row0 = blockIdx.y * 128, col0 = blockIdx.x * 128;

    float acc[2][8][4];
#pragma unroll
    for (int i = 0; i < 2; i++)
#pragma unroll
        for (int j = 0; j < 8; j++)
#pragma unroll
            for (int d = 0; d < 4; d++) acc[i][j][d] = 0.0f;

    int ldr = tid >> 2, lds = tid & 3;

    auto issue = [&](int c) {
        int s = c & 1;
        uint32_t st = sb + s * STAGE_B;
        int k0 = c * KC;
#pragma unroll
        for (int h = 0; h < 2; h++) {
            int r = ldr + h * 64;
            uint32_t off = (uint32_t)r * (SAB * 2) + lds * 16;
            CP_ASYNC16(st + off,              (const void*)(g_Fbf + (size_t)(row0 + r) * D + k0 + lds * 8));
            CP_ASYNC16(st + TILE_B + off,     (const void*)(g_Flo + (size_t)(row0 + r) * D + k0 + lds * 8));
            CP_ASYNC16(st + 2 * TILE_B + off, (const void*)(g_Wth + (size_t)(col0 + r) * 1024 + k0 + lds * 8));
            CP_ASYNC16(st + 3 * TILE_B + off, (const void*)(g_Wtl + (size_t)(col0 + r) * 1024 + k0 + lds * 8));
        }
    };

    int wm = wid & 3, wn = wid >> 2;
    int a_row = (lane & 7) + ((lane >> 3) & 1) * 8;
    int a_col = ((lane >> 4) & 1) * 8;
    int b_row = (lane & 7) + ((lane >> 4) & 1) * 8;
    int b_col = ((lane >> 3) & 1) * 8;

    issue(0); CP_COMMIT();
    for (int c = 0; c < NCK; c++) {
        if (c + 1 < NCK) { issue(c + 1); CP_COMMIT(); CP_WAIT(1); }
        else             { CP_WAIT(0); }
        __syncthreads();

        int s = c & 1;
        uint32_t Ahb = sb + s * STAGE_B + (uint32_t)(wm * 32) * (SAB * 2);
        uint32_t Alb = Ahb + TILE_B;
        uint32_t Bhb = sb + s * STAGE_B + 2 * TILE_B + (uint32_t)(wn * 64) * (SAB * 2);
        uint32_t Blb = Bhb + TILE_B;

        uint32_t ah[2][2][4], al[2][2][4];
#pragma unroll
        for (int i = 0; i < 2; i++)
#pragma unroll
            for (int st = 0; st < 2; st++) {
                uint32_t ro = (uint32_t)(i * 16 + a_row) * (SAB * 2)
                            + (uint32_t)(st * 16 + a_col) * 2;
                LDMX4(ah[i][st][0], ah[i][st][1], ah[i][st][2], ah[i][st][3], Ahb + ro);
                LDMX4(al[i][st][0], al[i][st][1], al[i][st][2], al[i][st][3], Alb + ro);
            }
#pragma unroll
        for (int jp = 0; jp < 4; jp++)
#pragma unroll
            for (int st = 0; st < 2; st++) {
                uint32_t ro = (uint32_t)(jp * 16 + b_row) * (SAB * 2)
                            + (uint32_t)(st * 16 + b_col) * 2;
                uint32_t bh[4], bl[4];
                LDMX4(bh[0], bh[1], bh[2], bh[3], Bhb + ro);
                LDMX4(bl[0], bl[1], bl[2], bl[3], Blb + ro);
#pragma unroll
                for (int i = 0; i < 2; i++)
#pragma unroll
                    for (int jh = 0; jh < 2; jh++) {
                        int j = jp * 2 + jh, hf = jh * 2;
                        MMA16816(acc[i][j], ah[i][st], bh[hf], bh[hf + 1]);
                        MMA16816(acc[i][j], al[i][st], bh[hf], bh[hf + 1]);
                        MMA16816(acc[i][j], ah[i][st], bl[hf], bl[hf + 1]);
                    }
            }
        __syncthreads();
    }

    int er = lane >> 2, ec = (lane & 3) * 2;
#pragma unroll
    for (int i = 0; i < 2; i++)
#pragma unroll
        for (int j = 0; j < 8; j++)
#pragma unroll
            for (int dp = 0; dp < 2; dp++) {
                int r = row0 + wm * 32 + i * 16 + dp * 8 + er;
                int c = col0 + wn * 64 + j * 8 + ec;
                if (c < OUTD) {
                    float2 v = make_float2(acc[i][j][dp * 2], acc[i][j][dp * 2 + 1]);
                    *(float2*)(g_S + (size_t)r * OUTD + c) = v;
                }
            }
}

// ---------------- sparse propagation: An @ X ---------------------------------
template <int MODE>
__global__ void spmm_kernel(const float* __restrict__ bias,
                            const float* __restrict__ gamma,
                            const float* __restrict__ beta,
                            const float* __restrict__ mean,
                            const float* __restrict__ var,
                            float* __restrict__ out) {
    int row = blockIdx.x, tid = threadIdx.x;
    float di = g_invd[row];
    float diag = di * di;
    const float* X = (MODE == 0) ? g_S : g_t1;
    const float* Xrow = X + (size_t)row * OUTD;
    int n0 = tid, n1 = tid + 256, n2 = tid + 512, n3 = tid + 768;
    float a0 = diag * Xrow[n0];
    float a1 = diag * Xrow[n1];
    float a2 = diag * Xrow[n2];
    float a3 = (n3 < OUTD) ? diag * Xrow[n3] : 0.0f;

    int nn = g_nnz[row];
    for (int e = 0; e < nn; e++) {
        float v = g_vals[(size_t)row * N + e];
        const float* Xc = X + (size_t)g_cols[(size_t)row * N + e] * OUTD;
        a0 += v * Xc[n0];
        a1 += v * Xc[n1];
        a2 += v * Xc[n2];
        if (n3 < OUTD) a3 += v * Xc[n3];
    }

    if (MODE == 0) {
        float* T = g_t1 + (size_t)row * OUTD;
        T[n0] = a0; T[n1] = a1; T[n2] = a2;
        if (n3 < OUTD) T[n3] = a3;
    } else {
        float c0 = g_coef[0], c1 = g_coef[1], c2 = g_coef[2];
        const float* Srow = g_S + (size_t)row * OUTD;
        const float* Trow = g_t1 + (size_t)row * OUTD;
        float* Orow = out + (size_t)row * OUTD;
        int ns[4] = {n0, n1, n2, n3};
        float as[4] = {a0, a1, a2, a3};
#pragma unroll
        for (int r = 0; r < 4; r++) {
            int n = ns[r];
            if (n < OUTD) {
                float x = c0 * Srow[n] + c1 * Trow[n] + c2 * as[r] + bias[n];
                float y = (x - mean[n]) * rsqrtf(var[n] + BN_EPS) * gamma[n] + beta[n];
                Orow[n] = fmaxf(y, 0.0f);
            }
        }
    }
}

// ---------------- launch -----------------------------------------------------
extern "C" void kernel_launch(void* const* d_in, const int* in_sizes, int n_in,
                              void* d_out, int out_size) {
    const float* F     = (const float*)d_in[0];
    const float* W     = (const float*)d_in[1];
    const float* bias  = (const float*)d_in[2];
    const float* a1    = (const float*)d_in[3];
    const float* a2    = (const float*)d_in[4];
    const float* a3    = (const float*)d_in[5];
    const float* gamma = (const float*)d_in[6];
    const float* beta  = (const float*)d_in[7];
    const float* mean  = (const float*)d_in[8];
    const float* var   = (const float*)d_in[9];
    float* out = (float*)d_out;

    const int GRAM_SMEM = 128 * 133 * 4;     // 68096 B (>= 4*TILE_B mainloop)
    const int SUP_SMEM  = 2 * STAGE_B;       // 81920 B
    static int configured = -1;
    if (configured < 0) {
        cudaFuncSetAttribute(gram_mma_kernel,
                             cudaFuncAttributeMaxDynamicSharedMemorySize, GRAM_SMEM);
        cudaFuncSetAttribute(support_mma_kernel,
                             cudaFuncAttributeMaxDynamicSharedMemorySize, SUP_SMEM);
        configured = 1;
    }

    init_kernel<<<16, 256>>>(a1, a2, a3);
    prep_F<<<N, 256>>>(F);
    prep_W<<<dim3(32, 32), dim3(32, 8)>>>(W);
    gram_mma_kernel<<<528, 256, GRAM_SMEM>>>();
    support_mma_kernel<<<dim3(8, 32), 256, SUP_SMEM>>>();
    thr_kernel<<<16, 256>>>();
    select_kernel<<<N, 256>>>();
    build_kernel<<<N, 256>>>();
    scale_kernel<<<N, 256>>>();
    spmm_kernel<0><<<N, 256>>>(bias, gamma, beta, mean, var, out);
    spmm_kernel<1><<<N, 256>>>(bias, gamma, beta, mean, var, out);
}

// round 7
// speedup vs baseline: 6.5752x; 1.1391x over previous
#include <cuda_runtime.h>
#include <cuda_bf16.h>
#include <math.h>
#include <stdint.h>

#define N 4096
#define D 1024
#define OUTD 1000
#define KSEL 819
#define BN_EPS 1e-5f

// ---------------- scratch (device globals; no allocations allowed) ----------
__device__ float g_sq[N];
__device__ __nv_bfloat16 g_Fbf[(size_t)N * D];   // bf16 hi of features
__device__ __nv_bfloat16 g_Flo[(size_t)N * D];   // bf16 lo residual
__device__ __nv_bfloat16 g_Wth[(size_t)1024 * 1024]; // W^T hi [n][k], n-padded
__device__ __nv_bfloat16 g_Wtl[(size_t)1024 * 1024]; // W^T lo
__device__ float g_Ae[(size_t)N * N];      // 64 MiB gaussian affinity
__device__ float g_thr[N];
__device__ float g_invd[N];
__device__ int   g_nnz[N];
__device__ int   g_poscnt[N];              // positives per Ae row (incl. diag)
__device__ int   g_cols[(size_t)N * N];
__device__ float g_vals[(size_t)N * N];
__device__ float g_S[(size_t)N * OUTD];
__device__ float g_t1[(size_t)N * OUTD];
__device__ float g_coef[3];
__device__ int   g_sel_cnt;
__device__ int   g_sel_rows[N];

// ---------------- baseline-PTX tensor-core helpers --------------------------
__device__ __forceinline__ uint32_t smem_u32(const void* p) {
    uint32_t a;
    asm("{ .reg .u64 t; cvta.to.shared.u64 t, %1; cvt.u32.u64 %0, t; }"
        : "=r"(a) : "l"(p));
    return a;
}
#define CP_ASYNC16(dst, src) \
    asm volatile("cp.async.cg.shared.global [%0], [%1], 16;" :: "r"(dst), "l"(src) : "memory")
#define CP_COMMIT() asm volatile("cp.async.commit_group;" ::: "memory")
#define CP_WAIT(n)  asm volatile("cp.async.wait_group %0;" :: "n"(n) : "memory")
#define LDMX4(r0, r1, r2, r3, addr) \
    asm volatile("ldmatrix.sync.aligned.m8n8.x4.shared.b16 {%0,%1,%2,%3}, [%4];" \
                 : "=r"(r0), "=r"(r1), "=r"(r2), "=r"(r3) : "r"(addr))
#define MMA16816(d, a, b0v, b1v) \
    asm volatile("mma.sync.aligned.m16n8k16.row.col.f32.bf16.bf16.f32 " \
                 "{%0,%1,%2,%3}, {%4,%5,%6,%7}, {%8,%9}, {%0,%1,%2,%3};" \
                 : "+f"((d)[0]), "+f"((d)[1]), "+f"((d)[2]), "+f"((d)[3]) \
                 : "r"((a)[0]), "r"((a)[1]), "r"((a)[2]), "r"((a)[3]), \
                   "r"(b0v), "r"(b1v))

// expf(-d2/9) underflows to exactly 0.0f for d2 >= 1000 (-d2/9 < -111)
#define D2_ZERO_CUT 1000.0f

#define KC 32
#define NC (D / KC)
#define SAB 40
#define TILE_B (128 * SAB * 2)     // 10240 bytes per operand tile
#define GSTG 4                      // gram pipeline stages (2 tiles/stage)
#define GSTAGE_B (2 * TILE_B)       // 20480
#define SSTAGE_B (4 * TILE_B)       // 40960 (support: 4 tiles/stage)
#define DUAL_SMEM 81920             // max(4*20480, 2*40960, epi 68096)
#define NGRAM 528

// ---------------- tiny kernels ----------------------------------------------
__global__ void init_kernel(const float* a1, const float* a2, const float* a3) {
    int i = blockIdx.x * 256 + threadIdx.x;
    if (i < N) g_poscnt[i] = 0;
    if (i == 0) {
        g_sel_cnt = 0;
        float x0 = a1[0], x1 = a2[0], x2 = a3[0];
        float m = fmaxf(x0, fmaxf(x1, x2));
        float e0 = expf(x0 - m), e1 = expf(x1 - m), e2 = expf(x2 - m);
        float s = e0 + e1 + e2;
        g_coef[0] = e0 / s; g_coef[1] = e1 / s; g_coef[2] = e2 / s;
    }
}

// one pass over F: row sq-norms + bf16 hi/lo split
__global__ void prep_F(const float* __restrict__ F) {
    int row = blockIdx.x, tid = threadIdx.x;
    float4 v = *(const float4*)(F + (size_t)row * D + tid * 4);
    float s = v.x * v.x + v.y * v.y + v.z * v.z + v.w * v.w;

    __nv_bfloat16 h0 = __float2bfloat16(v.x), h1 = __float2bfloat16(v.y);
    __nv_bfloat16 h2 = __float2bfloat16(v.z), h3 = __float2bfloat16(v.w);
    __nv_bfloat162 ph0, ph1, pl0, pl1;
    ph0.x = h0; ph0.y = h1; ph1.x = h2; ph1.y = h3;
    pl0.x = __float2bfloat16(v.x - __bfloat162float(h0));
    pl0.y = __float2bfloat16(v.y - __bfloat162float(h1));
    pl1.x = __float2bfloat16(v.z - __bfloat162float(h2));
    pl1.y = __float2bfloat16(v.w - __bfloat162float(h3));
    size_t o = (size_t)row * D + tid * 4;
    *(__nv_bfloat162*)(g_Fbf + o)     = ph0;
    *(__nv_bfloat162*)(g_Fbf + o + 2) = ph1;
    *(__nv_bfloat162*)(g_Flo + o)     = pl0;
    *(__nv_bfloat162*)(g_Flo + o + 2) = pl1;

    __shared__ float red[256];
    red[tid] = s; __syncthreads();
    for (int o2 = 128; o2 > 0; o2 >>= 1) {
        if (tid < o2) red[tid] += red[tid + o2];
        __syncthreads();
    }
    if (tid == 0) g_sq[row] = red[0];
}

// transpose W [k=1024][n=1000] -> Wt hi/lo [n=1024 pad][k=1024]
__global__ void prep_W(const float* __restrict__ W) {
    __shared__ float t[32][33];
    int nx = blockIdx.x * 32 + threadIdx.x;
#pragma unroll
    for (int s = 0; s < 4; s++) {
        int k = blockIdx.y * 32 + threadIdx.y + s * 8;
        t[threadIdx.y + s * 8][threadIdx.x] =
            (nx < OUTD) ? W[(size_t)k * OUTD + nx] : 0.0f;
    }
    __syncthreads();
#pragma unroll
    for (int s = 0; s < 4; s++) {
        int n_ = blockIdx.x * 32 + threadIdx.y + s * 8;
        int k_ = blockIdx.y * 32 + threadIdx.x;
        float w = t[threadIdx.x][threadIdx.y + s * 8];
        __nv_bfloat16 hi = __float2bfloat16(w);
        g_Wth[(size_t)n_ * 1024 + k_] = hi;
        g_Wtl[(size_t)n_ * 1024 + k_] = __float2bfloat16(w - __bfloat162float(hi));
    }
}

// ---------------- gram path: lower-tri 128x128 bf16 tiles, 4-stage ----------
__device__ __forceinline__ void gram_path(char* smem, int bid) {
    __shared__ int s_cr[128], s_cc[128];
    uint32_t sb = smem_u32(smem);
    int tid = threadIdx.x, wid = tid >> 5, lane = tid & 31;

    int tr = (int)((sqrtf(8.0f * (float)bid + 1.0f) - 1.0f) * 0.5f);
    while ((tr + 1) * (tr + 2) / 2 <= bid) tr++;
    while (tr * (tr + 1) / 2 > bid) tr--;
    int tc = bid - tr * (tr + 1) / 2;
    int row0 = tr * 128, col0 = tc * 128;

    const __nv_bfloat16* Ag = g_Fbf + (size_t)row0 * D;
    const __nv_bfloat16* Bg = g_Fbf + (size_t)col0 * D;

    float acc[2][8][4];
#pragma unroll
    for (int i = 0; i < 2; i++)
#pragma unroll
        for (int j = 0; j < 8; j++)
#pragma unroll
            for (int d = 0; d < 4; d++) acc[i][j][d] = 0.0f;

    int ldr = tid >> 2, lds = tid & 3;

    auto issue = [&](int c) {             // slot by raw c, data chunk clamped
        int s = c & (GSTG - 1);
        int cc = (c < NC) ? c : (NC - 1);
        uint32_t dstA = sb + s * GSTAGE_B;
        uint32_t dstB = dstA + TILE_B;
        int k0 = cc * KC;
#pragma unroll
        for (int h = 0; h < 2; h++) {
            int r = ldr + h * 64;
            uint32_t off = (uint32_t)r * (SAB * 2) + lds * 16;
            CP_ASYNC16(dstA + off, (const void*)(Ag + (size_t)r * D + k0 + lds * 8));
            CP_ASYNC16(dstB + off, (const void*)(Bg + (size_t)r * D + k0 + lds * 8));
        }
        CP_COMMIT();
    };

    int wm = wid & 3, wn = wid >> 2;
    int a_row = (lane & 7) + ((lane >> 3) & 1) * 8;
    int a_col = ((lane >> 4) & 1) * 8;
    int b_row = (lane & 7) + ((lane >> 4) & 1) * 8;
    int b_col = ((lane >> 3) & 1) * 8;

    issue(0); issue(1); issue(2);
    for (int c = 0; c < NC; c++) {
        CP_WAIT(2);                   // stage c landed (always 3 newest pending)
        __syncthreads();              // all warps done with slot (c-1)%4
        issue(c + 3);                 // overwrite slot (c-1)%4; loads fly during compute

        int s = c & (GSTG - 1);
        uint32_t Abase = sb + s * GSTAGE_B + (uint32_t)(wm * 32) * (SAB * 2);
        uint32_t Bbase = sb + s * GSTAGE_B + TILE_B + (uint32_t)(wn * 64) * (SAB * 2);

        uint32_t a[2][2][4];
#pragma unroll
        for (int i = 0; i < 2; i++)
#pragma unroll
            for (int st = 0; st < 2; st++) {
                uint32_t ad = Abase + (uint32_t)(i * 16 + a_row) * (SAB * 2)
                            + (uint32_t)(st * 16 + a_col) * 2;
                LDMX4(a[i][st][0], a[i][st][1], a[i][st][2], a[i][st][3], ad);
            }
        uint32_t b[4][2][4];
#pragma unroll
        for (int jp = 0; jp < 4; jp++)
#pragma unroll
            for (int st = 0; st < 2; st++) {
                uint32_t bd = Bbase + (uint32_t)(jp * 16 + b_row) * (SAB * 2)
                            + (uint32_t)(st * 16 + b_col) * 2;
                LDMX4(b[jp][st][0], b[jp][st][1], b[jp][st][2], b[jp][st][3], bd);
            }
#pragma unroll
        for (int i = 0; i < 2; i++)
#pragma unroll
            for (int j = 0; j < 8; j++) {
                int jp = j >> 1, hf = (j & 1) * 2;
#pragma unroll
                for (int st = 0; st < 2; st++)
                    MMA16816(acc[i][j], a[i][st], b[jp][st][hf], b[jp][st][hf + 1]);
            }
        // no trailing sync: next iteration's sync protects the reused slot
    }
    CP_WAIT(0);                       // drain trailing redundant loads
    if (tid < 128) { s_cr[tid] = 0; s_cc[tid] = 0; }
    __syncthreads();                  // compute done + counters zeroed before epi

    float* epi = (float*)smem;
    int er = lane >> 2, ec = (lane & 3) * 2;
#pragma unroll
    for (int i = 0; i < 2; i++)
#pragma unroll
        for (int j = 0; j < 8; j++)
#pragma unroll
            for (int d = 0; d < 4; d++) {
                int r = wm * 32 + i * 16 + (d >> 1) * 8 + er;
                int cc = wn * 64 + j * 8 + ec + (d & 1);
                float d2 = fmaxf(g_sq[row0 + r] + g_sq[col0 + cc] - 2.0f * acc[i][j][d], 0.0f);
                float e = 0.0f;
                if (d2 < D2_ZERO_CUT) {
                    e = expf(-d2 / 9.0f);
                    if (e > 0.0f) {
                        atomicAdd(&s_cr[r], 1);
                        if (tr != tc) atomicAdd(&s_cc[cc], 1);
                    }
                }
                epi[r * 133 + cc] = e;
            }
    __syncthreads();

    for (int rr = wid * 16; rr < wid * 16 + 16; rr++) {
        float4 v;
        v.x = epi[rr * 133 + lane * 4 + 0];
        v.y = epi[rr * 133 + lane * 4 + 1];
        v.z = epi[rr * 133 + lane * 4 + 2];
        v.w = epi[rr * 133 + lane * 4 + 3];
        *(float4*)(g_Ae + (size_t)(row0 + rr) * N + col0 + lane * 4) = v;
    }
    for (int cc = wid * 16; cc < wid * 16 + 16; cc++) {
        float4 v;
        v.x = epi[(lane * 4 + 0) * 133 + cc];
        v.y = epi[(lane * 4 + 1) * 133 + cc];
        v.z = epi[(lane * 4 + 2) * 133 + cc];
        v.w = epi[(lane * 4 + 3) * 133 + cc];
        *(float4*)(g_Ae + (size_t)(col0 + cc) * N + row0 + lane * 4) = v;
    }
    if (tid < 128) {
        if (s_cr[tid]) atomicAdd(&g_poscnt[row0 + tid], s_cr[tid]);
        if (tr != tc && s_cc[tid]) atomicAdd(&g_poscnt[col0 + tid], s_cc[tid]);
    }
}

// ---------------- support path: S = F @ W, bf16 split-2, 2-stage ------------
__device__ __forceinline__ void support_path(char* smem, int sid) {
    uint32_t sb = smem_u32(smem);
    int tid = threadIdx.x, wid = tid >> 5, lane = tid & 31;
    int row0 = (sid >> 3) * 128, col0 = (sid & 7) * 128;

    float acc[2][8][4];
#pragma unroll
    for (int i = 0; i < 2; i++)
#pragma unroll
        for (int j = 0; j < 8; j++)
#pragma unroll
            for (int d = 0; d < 4; d++) acc[i][j][d] = 0.0f;

    int ldr = tid >> 2, lds = tid & 3;

    auto issue = [&](int c) {
        int s = c & 1;
        uint32_t st = sb + s * SSTAGE_B;
        int k0 = c * KC;
#pragma unroll
        for (int h = 0; h < 2; h++) {
            int r = ldr + h * 64;
            uint32_t off = (uint32_t)r * (SAB * 2) + lds * 16;
            CP_ASYNC16(st + off,              (const void*)(g_Fbf + (size_t)(row0 + r) * D + k0 + lds * 8));
            CP_ASYNC16(st + TILE_B + off,     (const void*)(g_Flo + (size_t)(row0 + r) * D + k0 + lds * 8));
            CP_ASYNC16(st + 2 * TILE_B + off, (const void*)(g_Wth + (size_t)(col0 + r) * 1024 + k0 + lds * 8));
            CP_ASYNC16(st + 3 * TILE_B + off, (const void*)(g_Wtl + (size_t)(col0 + r) * 1024 + k0 + lds * 8));
        }
        CP_COMMIT();
    };

    int wm = wid & 3, wn = wid >> 2;
    int a_row = (lane & 7) + ((lane >> 3) & 1) * 8;
    int a_col = ((lane >> 4) & 1) * 8;
    int b_row = (lane & 7) + ((lane >> 4) & 1) * 8;
    int b_col = ((lane >> 3) & 1) * 8;

    issue(0);
    for (int c = 0; c < NC; c++) {
        CP_WAIT(0);                   // stage c landed
        __syncthreads();              // slot (c-1)&1 fully consumed
        if (c + 1 < NC) issue(c + 1); // overwrite slot (c+1)&1 == (c-1)&1

        int s = c & 1;
        uint32_t Ahb = sb + s * SSTAGE_B + (uint32_t)(wm * 32) * (SAB * 2);
        uint32_t Alb = Ahb + TILE_B;
        uint32_t Bhb = sb + s * SSTAGE_B + 2 * TILE_B + (uint32_t)(wn * 64) * (SAB * 2);
        uint32_t Blb = Bhb + TILE_B;

        uint32_t ah[2][2][4], al[2][2][4];
#pragma unroll
        for (int i = 0; i < 2; i++)
#pragma unroll
            for (int st = 0; st < 2; st++) {
                uint32_t ro = (uint32_t)(i * 16 + a_row) * (SAB * 2)
                            + (uint32_t)(st * 16 + a_col) * 2;
                LDMX4(ah[i][st][0], ah[i][st][1], ah[i][st][2], ah[i][st][3], Ahb + ro);
                LDMX4(al[i][st][0], al[i][st][1], al[i][st][2], al[i][st][3], Alb + ro);
            }
#pragma unroll
        for (int jp = 0; jp < 4; jp++)
#pragma unroll
            for (int st = 0; st < 2; st++) {
                uint32_t ro = (uint32_t)(jp * 16 + b_row) * (SAB * 2)
                            + (uint32_t)(st * 16 + b_col) * 2;
                uint32_t bh[4], bl[4];
                LDMX4(bh[0], bh[1], bh[2], bh[3], Bhb + ro);
                LDMX4(bl[0], bl[1], bl[2], bl[3], Blb + ro);
#pragma unroll
                for (int i = 0; i < 2; i++)
#pragma unroll
                    for (int jh = 0; jh < 2; jh++) {
                        int j = jp * 2 + jh, hf = jh * 2;
                        MMA16816(acc[i][j], ah[i][st], bh[hf], bh[hf + 1]);
                        MMA16816(acc[i][j], al[i][st], bh[hf], bh[hf + 1]);
                        MMA16816(acc[i][j], ah[i][st], bl[hf], bl[hf + 1]);
                    }
            }
    }

    int er = lane >> 2, ec = (lane & 3) * 2;
#pragma unroll
    for (int i = 0; i < 2; i++)
#pragma unroll
        for (int j = 0; j < 8; j++)
#pragma unroll
            for (int dp = 0; dp < 2; dp++) {
                int r = row0 + wm * 32 + i * 16 + dp * 8 + er;
                int c = col0 + wn * 64 + j * 8 + ec;
                if (c < OUTD) {
                    float2 v = make_float2(acc[i][j][dp * 2], acc[i][j][dp * 2 + 1]);
                    *(float2*)(g_S + (size_t)r * OUTD + c) = v;
                }
            }
}

// ---------------- merged GEMM kernel (gram tiles + support tiles) -----------
__global__ void __launch_bounds__(256, 2) dual_mma_kernel() {
    extern __shared__ char smem[];
    if (blockIdx.x < NGRAM) gram_path(smem, blockIdx.x);
    else                    support_path(smem, blockIdx.x - NGRAM);
}

// ---------------- threshold dispatch from fused counts ----------------------
__global__ void thr_kernel() {
    int row = blockIdx.x * 256 + threadIdx.x;
    if (row >= N) return;
    if (g_poscnt[row] < KSEL) {
        g_thr[row] = 0.0f;
    } else {
        int idx = atomicAdd(&g_sel_cnt, 1);
        g_sel_rows[idx] = row;
    }
}

// ---------------- full radix select (only rows with >= K positives) ---------
__global__ void select_kernel() {
    __shared__ unsigned v[N];
    __shared__ int hist[256];
    __shared__ int sfx[256];
    __shared__ int s_bin, s_rem;
    if (blockIdx.x >= g_sel_cnt) return;
    int row = g_sel_rows[blockIdx.x];
    int tid = threadIdx.x, lane = tid & 31;
    for (int i = tid; i < N; i += 256)
        v[i] = __float_as_uint(g_Ae[(size_t)row * N + i]);
    __syncthreads();

    unsigned prefix = 0;
    int remaining = KSEL;
    for (int shift = 24; shift >= 0; shift -= 8) {
        hist[tid] = 0;
        __syncthreads();
        unsigned hm = (shift == 24) ? 0u : (0xFFFFFFFFu << (shift + 8));
        unsigned ph = prefix & hm;
#pragma unroll
        for (int i = tid; i < N; i += 256) {
            unsigned x = v[i];
            bool act = ((x & hm) == ph);
            int bin = (x >> shift) & 255;
            unsigned key = act ? (unsigned)bin : 0xFFFFFFFFu;
            unsigned mask = __match_any_sync(0xFFFFFFFFu, key);
            if (act && ((__ffs(mask) - 1) == lane))
                atomicAdd(&hist[bin], __popc(mask));
        }
        __syncthreads();
        sfx[tid] = hist[tid];
        __syncthreads();
        for (int off = 1; off < 256; off <<= 1) {
            int val = (tid + off < 256) ? sfx[tid + off] : 0;
            __syncthreads();
            sfx[tid] += val;
            __syncthreads();
        }
        int nb = (tid < 255) ? sfx[tid + 1] : 0;
        if (sfx[tid] >= remaining && nb < remaining) {
            s_bin = tid;
            s_rem = remaining - nb;
        }
        __syncthreads();
        prefix |= ((unsigned)s_bin) << shift;
        remaining = s_rem;
        __syncthreads();
    }
    if (tid == 0) g_thr[row] = __uint_as_float(prefix);
}

// ---------------- build sparse A (raw Ae vals), degrees ---------------------
__global__ void build_kernel() {
    int row = blockIdx.x, tid = threadIdx.x;
    if (g_poscnt[row] == 1) {   // only diagonal positive
        if (tid == 0) { g_nnz[row] = 0; g_invd[row] = rsqrtf(2.0f); }
        return;
    }
    float ti = g_thr[row];
    __shared__ int   cnt[256];
    __shared__ float ssum[256];
    __shared__ int   excl[257];
    int base = tid * 16;
    int lc = 0; float ls = 0.0f;
    for (int jj = 0; jj < 16; jj++) {
        int j = base + jj;
        float w = g_Ae[(size_t)row * N + j];
        if (j != row && w > 0.0f && w >= ti && w >= g_thr[j]) { lc++; ls += w; }
    }
    cnt[tid] = lc; ssum[tid] = ls;
    __syncthreads();
    if (tid == 0) {
        int run = 0; float tot = 0.0f;
        for (int t = 0; t < 256; t++) { excl[t] = run; run += cnt[t]; tot += ssum[t]; }
        excl[256] = run;
        g_nnz[row]  = run;
        g_invd[row] = rsqrtf(2.0f + tot);
    }
    __syncthreads();
    int off = excl[tid];
    for (int jj = 0; jj < 16; jj++) {
        int j = base + jj;
        float w = g_Ae[(size_t)row * N + j];
        if (j != row && w > 0.0f && w >= ti && w >= g_thr[j]) {
            g_cols[(size_t)row * N + off] = j;
            g_vals[(size_t)row * N + off] = w;
            off++;
        }
    }
}

__global__ void scale_kernel() {
    int row = blockIdx.x;
    int nn = g_nnz[row];
    float di = g_invd[row];
    for (int e = threadIdx.x; e < nn; e += 256) {
        size_t idx = (size_t)row * N + e;
        g_vals[idx] *= di * g_invd[g_cols[idx]];
    }
}

// ---------------- sparse propagation ----------------------------------------
// mutual-kNN is symmetric: a row with nnz==0 is referenced by no other row,
// so t1 only needs materializing for nnz>0 rows.
__global__ void spmmA_kernel() {
    int row = blockIdx.x, tid = threadIdx.x;
    int nn = g_nnz[row];
    if (nn == 0) return;
    float di = g_invd[row];
    float diag = di * di;
    const float* Xrow = g_S + (size_t)row * OUTD;
    int n0 = tid, n1 = tid + 256, n2 = tid + 512, n3 = tid + 768;
    float a0 = diag * Xrow[n0];
    float a1 = diag * Xrow[n1];
    float a2 = diag * Xrow[n2];
    float a3 = (n3 < OUTD) ? diag * Xrow[n3] : 0.0f;
    for (int e = 0; e < nn; e++) {
        float v = g_vals[(size_t)row * N + e];
        const float* Xc = g_S + (size_t)g_cols[(size_t)row * N + e] * OUTD;
        a0 += v * Xc[n0];
        a1 += v * Xc[n1];
        a2 += v * Xc[n2];
        if (n3 < OUTD) a3 += v * Xc[n3];
    }
    float* T = g_t1 + (size_t)row * OUTD;
    T[n0] = a0; T[n1] = a1; T[n2] = a2;
    if (n3 < OUTD) T[n3] = a3;
}

__global__ void spmmB_kernel(const float* __restrict__ bias,
                             const float* __restrict__ gamma,
                             const float* __restrict__ beta,
                             const float* __restrict__ mean,
                             const float* __restrict__ var,
                             float* __restrict__ out) {
    int row = blockIdx.x, tid = threadIdx.x;
    int nn = g_nnz[row];
    float di = g_invd[row];
    float diag = di * di;
    float c0 = g_coef[0], c1 = g_coef[1], c2 = g_coef[2];
    const float* Srow = g_S + (size_t)row * OUTD;
    float* Orow = out + (size_t)row * OUTD;

    if (nn == 0) {
        // local: t1 = diag*s; An@t1 = diag*t1  (same op sequence as 2-pass)
#pragma unroll
        for (int q = 0; q < 4; q++) {
            int n = tid + q * 256;
            if (n < OUTD) {
                float s = Srow[n];
                float t = diag * s;
                float a = diag * t;
                float x = c0 * s + c1 * t + c2 * a + bias[n];
                float y = (x - mean[n]) * rsqrtf(var[n] + BN_EPS) * gamma[n] + beta[n];
                Orow[n] = fmaxf(y, 0.0f);
            }
        }
        return;
    }

    const float* Trow = g_t1 + (size_t)row * OUTD;
    int n0 = tid, n1 = tid + 256, n2 = tid + 512, n3 = tid + 768;
    float a0 = diag * Trow[n0];
    float a1 = diag * Trow[n1];
    float a2 = diag * Trow[n2];
    float a3 = (n3 < OUTD) ? diag * Trow[n3] : 0.0f;
    for (int e = 0; e < nn; e++) {
        float v = g_vals[(size_t)row * N + e];
        const float* Xc = g_t1 + (size_t)g_cols[(size_t)row * N + e] * OUTD;
        a0 += v * Xc[n0];
        a1 += v * Xc[n1];
        a2 += v * Xc[n2];
        if (n3 < OUTD) a3 += v * Xc[n3];
    }
    int ns[4] = {n0, n1, n2, n3};
    float as[4] = {a0, a1, a2, a3};
#pragma unroll
    for (int r = 0; r < 4; r++) {
        int n = ns[r];
        if (n < OUTD) {
            float x = c0 * Srow[n] + c1 * Trow[n] + c2 * as[r] + bias[n];
            float y = (x - mean[n]) * rsqrtf(var[n] + BN_EPS) * gamma[n] + beta[n];
            Orow[n] = fmaxf(y, 0.0f);
        }
    }
}

// ---------------- launch -----------------------------------------------------
extern "C" void kernel_launch(void* const* d_in, const int* in_sizes, int n_in,
                              void* d_out, int out_size) {
    const float* F     = (const float*)d_in[0];
    const float* W     = (const float*)d_in[1];
    const float* bias  = (const float*)d_in[2];
    const float* a1    = (const float*)d_in[3];
    const float* a2    = (const float*)d_in[4];
    const float* a3    = (const float*)d_in[5];
    const float* gamma = (const float*)d_in[6];
    const float* beta  = (const float*)d_in[7];
    const float* mean  = (const float*)d_in[8];
    const float* var   = (const float*)d_in[9];
    float* out = (float*)d_out;

    static int configured = -1;
    if (configured < 0) {
        cudaFuncSetAttribute(dual_mma_kernel,
                             cudaFuncAttributeMaxDynamicSharedMemorySize, DUAL_SMEM);
        configured = 1;
    }

    init_kernel<<<16, 256>>>(a1, a2, a3);
    prep_F<<<N, 256>>>(F);
    prep_W<<<dim3(32, 32), dim3(32, 8)>>>(W);
    dual_mma_kernel<<<NGRAM + 256, 256, DUAL_SMEM>>>();
    thr_kernel<<<16, 256>>>();
    select_kernel<<<N, 256>>>();
    build_kernel<<<N, 256>>>();
    scale_kernel<<<N, 256>>>();
    spmmA_kernel<<<N, 256>>>();
    spmmB_kernel<<<N, 256>>>(bias, gamma, beta, mean, var, out);
}